// round 1
// baseline (speedup 1.0000x reference)
#include <cuda_runtime.h>
#include <cuda_bf16.h>

// ---------------------------------------------------------------------------
// QAttention: quaternion-conv attention block
//   x (2,128,128,128) -> qkv 1x1 qconv (384ch) -> 3x3 qconv (384ch)
//   -> split q,k,v (b,4,32,16384), L2-normalize q,k over s
//   -> attn = softmax(q k^T * temp) ; out = attn @ v
//   -> 1x1 qconv (128ch) -> d_out
// All fp32 CUDA-core baseline. Dominant cost: 3x3 conv = 43.5 GMAC.
// ---------------------------------------------------------------------------

#define SPX 16384           // H*W
#define NB  2               // batch

// ------------------- device scratch (no allocations allowed) ----------------
__device__ float g_Wqkv[384 * 128];
__device__ float g_Wdw [9 * 384 * 384];   // [tap][oc][ic]
__device__ float g_Wpo [128 * 128];
__device__ float g_y1  [NB * 384 * SPX];
__device__ float g_y2  [NB * 384 * SPX];
__device__ float g_ao  [NB * 128 * SPX];
__device__ float g_scale[NB * 256];       // [b][{q=0,k=1}*128 + ch]  inv-norms
__device__ float g_G   [NB * 4 * 1024];   // raw gram per (b,h): 32x32
__device__ float g_A   [NB * 4 * 1024];   // softmaxed attn

// Hamilton block table:
// row_r=[ r,-i,-j,-k]  row_i=[ i, r,-k, j]  row_j=[ j, k, r,-i]  row_k=[ k,-j, i, r]
__device__ __forceinline__ void ham(int bo, int bi, int& src, float& sgn) {
    const int   SRC[4][4] = {{0,1,2,3},{1,0,3,2},{2,3,0,1},{3,2,1,0}};
    const float SGN[4][4] = {{1.f,-1.f,-1.f,-1.f},
                             {1.f, 1.f,-1.f, 1.f},
                             {1.f, 1.f, 1.f,-1.f},
                             {1.f,-1.f, 1.f, 1.f}};
    src = SRC[bo][bi];
    sgn = SGN[bo][bi];
}

// ------------------- weight expansion + G zero ------------------------------
// 288 blocks x 256 thr = 73728 = 49152 (Wqkv) + 16384 (Wpo) + 8192 (G zero)
__global__ void expand_small(const float* __restrict__ qr, const float* __restrict__ qi,
                             const float* __restrict__ qj, const float* __restrict__ qk,
                             const float* __restrict__ pr, const float* __restrict__ pi,
                             const float* __restrict__ pj, const float* __restrict__ pk)
{
    int t = blockIdx.x * 256 + threadIdx.x;
    if (t < 49152) {
        int oc = t >> 7, ic = t & 127;
        int bo = oc / 96, oo = oc - bo * 96;
        int bi = ic >> 5, ii = ic & 31;
        const float* srcs[4] = {qr, qi, qj, qk};
        int s; float sg; ham(bo, bi, s, sg);
        g_Wqkv[t] = sg * srcs[s][oo * 32 + ii];
    } else if (t < 65536) {
        int e = t - 49152;
        int oc = e >> 7, ic = e & 127;
        int bo = oc >> 5, oo = oc & 31;
        int bi = ic >> 5, ii = ic & 31;
        const float* srcs[4] = {pr, pi, pj, pk};
        int s; float sg; ham(bo, bi, s, sg);
        g_Wpo[e] = sg * srcs[s][oo * 32 + ii];
    } else {
        g_G[t - 65536] = 0.f;
    }
}

// 5184 blocks x 256 thr = 1327104 = 9*384*384 elems
__global__ void expand_dw(const float* __restrict__ dr, const float* __restrict__ di,
                          const float* __restrict__ dj, const float* __restrict__ dk)
{
    int t = blockIdx.x * 256 + threadIdx.x;
    int oc  = t / 3456;
    int rem = t - oc * 3456;
    int ic  = rem / 9;
    int tap = rem - ic * 9;
    int bo = oc / 96, oo = oc - bo * 96;
    int bi = ic / 96, ii = ic - bi * 96;
    const float* srcs[4] = {dr, di, dj, dk};
    int s; float sg; ham(bo, bi, s, sg);
    g_Wdw[tap * 147456 + oc * 384 + ic] = sg * srcs[s][(oo * 96 + ii) * 9 + tap];
}

// ------------------- 1x1 conv GEMM (K=128) ----------------------------------
// mode 0: W=g_Wqkv (M=384), B=x,    C=g_y1
// mode 1: W=g_Wpo  (M=128), B=g_ao, C=d_out
// tile 64x64, BK=16, 4x4 per thread, 256 threads
__global__ void gemm1x1(int mode, const float* __restrict__ Xin, float* __restrict__ Oout,
                        const float* __restrict__ bias)
{
    __shared__ __align__(16) float As[16][68];
    __shared__ __align__(16) float Bs[16][64];
    const float* W; const float* B; float* C; int cbs;
    if (mode == 0) { W = g_Wqkv; B = Xin;  C = g_y1; cbs = 384 * SPX; }
    else           { W = g_Wpo;  B = g_ao; C = Oout; cbs = 128 * SPX; }

    int b  = blockIdx.z;
    int m0 = blockIdx.x * 64, n0 = blockIdx.y * 64;
    int tid = threadIdx.x;
    int tx4 = (tid & 15) * 4, ty4 = (tid >> 4) * 4;
    int lm  = tid >> 2,  lk4 = (tid & 3) * 4;
    int lk  = tid >> 4,  ln4 = (tid & 15) * 4;
    const float* Bb = B + b * 128 * SPX;

    float acc[4][4];
#pragma unroll
    for (int i = 0; i < 4; i++)
#pragma unroll
        for (int j = 0; j < 4; j++) acc[i][j] = 0.f;

    for (int k0 = 0; k0 < 128; k0 += 16) {
        float4 a4 = *(const float4*)&W[(m0 + lm) * 128 + k0 + lk4];
        As[lk4 + 0][lm] = a4.x; As[lk4 + 1][lm] = a4.y;
        As[lk4 + 2][lm] = a4.z; As[lk4 + 3][lm] = a4.w;
        *(float4*)&Bs[lk][ln4] = *(const float4*)&Bb[(k0 + lk) * SPX + n0 + ln4];
        __syncthreads();
#pragma unroll
        for (int kk = 0; kk < 16; kk++) {
            float4 av = *(const float4*)&As[kk][ty4];
            float4 bv = *(const float4*)&Bs[kk][tx4];
            float a_[4] = {av.x, av.y, av.z, av.w};
            float b_[4] = {bv.x, bv.y, bv.z, bv.w};
#pragma unroll
            for (int i = 0; i < 4; i++)
#pragma unroll
                for (int j = 0; j < 4; j++) acc[i][j] += a_[i] * b_[j];
        }
        __syncthreads();
    }
    float* Cb = C + b * cbs;
#pragma unroll
    for (int i = 0; i < 4; i++) {
        float bs = bias[m0 + ty4 + i];
        float4 v = make_float4(acc[i][0] + bs, acc[i][1] + bs, acc[i][2] + bs, acc[i][3] + bs);
        *(float4*)&Cb[(m0 + ty4 + i) * SPX + n0 + tx4] = v;
    }
}

// ------------------- 3x3 conv: 9 shifted GEMMs, fused ------------------------
// grid (6 oc-tiles, 256 = h*2+wtile, 2 batch); 64oc x 64px tile
__global__ void conv3x3(const float* __restrict__ bias)
{
    __shared__ __align__(16) float As[16][68];
    __shared__ __align__(16) float Bs[16][64];
    int b   = blockIdx.z;
    int oc0 = blockIdx.x * 64;
    int h   = blockIdx.y >> 1;
    int w0  = (blockIdx.y & 1) << 6;
    int tid = threadIdx.x;
    int tx4 = (tid & 15) * 4, ty4 = (tid >> 4) * 4;
    int lm  = tid >> 2,  lk4 = (tid & 3) * 4;
    int lk  = tid >> 4,  ln4 = (tid & 15) * 4;
    const float* y1b = g_y1 + b * 384 * SPX;

    float acc[4][4];
#pragma unroll
    for (int i = 0; i < 4; i++)
#pragma unroll
        for (int j = 0; j < 4; j++) acc[i][j] = 0.f;

    for (int tap = 0; tap < 9; tap++) {
        int dh = tap / 3 - 1, dwd = tap % 3 - 1;
        int hh = h + dh;
        bool rowok = ((unsigned)hh < 128u);
        const float* Wt   = g_Wdw + tap * 147456;
        const float* brow = y1b + hh * 128;
        for (int k0 = 0; k0 < 384; k0 += 16) {
            float4 a4 = *(const float4*)&Wt[(oc0 + lm) * 384 + k0 + lk4];
            As[lk4 + 0][lm] = a4.x; As[lk4 + 1][lm] = a4.y;
            As[lk4 + 2][lm] = a4.z; As[lk4 + 3][lm] = a4.w;
            int ic = k0 + lk;
#pragma unroll
            for (int e = 0; e < 4; e++) {
                int w = w0 + ln4 + e + dwd;
                float v = 0.f;
                if (rowok && (unsigned)w < 128u) v = brow[ic * SPX + w];
                Bs[lk][ln4 + e] = v;
            }
            __syncthreads();
#pragma unroll
            for (int kk = 0; kk < 16; kk++) {
                float4 av = *(const float4*)&As[kk][ty4];
                float4 bv = *(const float4*)&Bs[kk][tx4];
                float a_[4] = {av.x, av.y, av.z, av.w};
                float b_[4] = {bv.x, bv.y, bv.z, bv.w};
#pragma unroll
                for (int i = 0; i < 4; i++)
#pragma unroll
                    for (int j = 0; j < 4; j++) acc[i][j] += a_[i] * b_[j];
            }
            __syncthreads();
        }
    }
    float* outb = g_y2 + b * 384 * SPX + h * 128 + w0;
#pragma unroll
    for (int i = 0; i < 4; i++) {
        float bs = bias[oc0 + ty4 + i];
        float4 v = make_float4(acc[i][0] + bs, acc[i][1] + bs, acc[i][2] + bs, acc[i][3] + bs);
        *(float4*)&outb[(oc0 + ty4 + i) * SPX + tx4] = v;
    }
}

// ------------------- inverse L2 norms for q,k -------------------------------
// 512 blocks: [b][qk][ch]; 256 threads sum 16384 elems (float4)
__global__ void norms_kernel()
{
    int bi_ = blockIdx.x;
    int ch = bi_ & 127, qk = (bi_ >> 7) & 1, b = bi_ >> 8;
    const float4* p = (const float4*)(g_y2 + b * 384 * SPX + (qk * 128 + ch) * SPX);
    float ss = 0.f;
    for (int i = threadIdx.x; i < 4096; i += 256) {
        float4 v = p[i];
        ss += v.x * v.x + v.y * v.y + v.z * v.z + v.w * v.w;
    }
    __shared__ float red[256];
    red[threadIdx.x] = ss;
    __syncthreads();
    for (int o = 128; o > 0; o >>= 1) {
        if (threadIdx.x < o) red[threadIdx.x] += red[threadIdx.x + o];
        __syncthreads();
    }
    if (threadIdx.x == 0) g_scale[bi_] = 1.f / fmaxf(sqrtf(red[0]), 1e-12f);
}

// ------------------- raw gram q k^T (s-split + atomics) ----------------------
// 1024 blocks: [b][h][split of 128 s]; thread -> (c, d0..d0+3)
__global__ void gram_kernel()
{
    __shared__ float Qs[32 * 129];
    __shared__ float Ks[32 * 129];
    int bi_ = blockIdx.x;
    int split = bi_ & 127;
    int h = (bi_ >> 7) & 3;
    int b = bi_ >> 9;
    int s0 = split * 128;
    const float* gQ = g_y2 + b * 384 * SPX + (h * 32) * SPX + s0;
    const float* gK = gQ + 128 * SPX;
    int tid = threadIdx.x;
    for (int idx = tid; idx < 4096; idx += 256) {
        int row = idx >> 7, col = idx & 127;
        Qs[row * 129 + col] = gQ[row * SPX + col];
        Ks[row * 129 + col] = gK[row * SPX + col];
    }
    __syncthreads();
    int c = tid >> 3, d0 = (tid & 7) * 4;
    float a0 = 0.f, a1 = 0.f, a2 = 0.f, a3 = 0.f;
    const float* qrow = &Qs[c * 129];
#pragma unroll 4
    for (int s = 0; s < 128; s++) {
        float qv = qrow[s];
        a0 += qv * Ks[(d0 + 0) * 129 + s];
        a1 += qv * Ks[(d0 + 1) * 129 + s];
        a2 += qv * Ks[(d0 + 2) * 129 + s];
        a3 += qv * Ks[(d0 + 3) * 129 + s];
    }
    float* Gp = &g_G[(b * 4 + h) * 1024 + c * 32 + d0];
    atomicAdd(Gp + 0, a0); atomicAdd(Gp + 1, a1);
    atomicAdd(Gp + 2, a2); atomicAdd(Gp + 3, a3);
}

// ------------------- scale + softmax over d ---------------------------------
// 256 blocks = (b,h,c); 32 threads = d
__global__ void softmax_kernel(const float* __restrict__ temp)
{
    int bi_ = blockIdx.x;
    int c = bi_ & 31;
    int bh = bi_ >> 5;
    int h = bh & 3, b = bh >> 2;
    int d = threadIdx.x;
    float g = g_G[bh * 1024 + c * 32 + d]
            * g_scale[b * 256 + h * 32 + c]
            * g_scale[b * 256 + 128 + h * 32 + d]
            * temp[h];
    float mx = g;
    for (int o = 16; o > 0; o >>= 1) mx = fmaxf(mx, __shfl_xor_sync(0xffffffffu, mx, o));
    float e = expf(g - mx);
    float sm = e;
    for (int o = 16; o > 0; o >>= 1) sm += __shfl_xor_sync(0xffffffffu, sm, o);
    g_A[bh * 1024 + c * 32 + d] = e / sm;
}

// ------------------- out = attn @ v ------------------------------------------
// 512 blocks = (b,h, stile of 256); thread = one s, 32 v in regs
__global__ void attnv_kernel()
{
    __shared__ float Asm[1024];
    int bi_ = blockIdx.x;
    int st = bi_ & 63;
    int h = (bi_ >> 6) & 3;
    int b = bi_ >> 8;
    int tid = threadIdx.x;
    int bh = b * 4 + h;
    for (int idx = tid; idx < 1024; idx += 256) Asm[idx] = g_A[bh * 1024 + idx];
    __syncthreads();
    int s = st * 256 + tid;
    const float* vb = g_y2 + b * 384 * SPX + (256 + h * 32) * SPX + s;
    float vreg[32];
#pragma unroll
    for (int d = 0; d < 32; d++) vreg[d] = vb[d * SPX];
    float* ob = g_ao + b * 128 * SPX + (h * 32) * SPX + s;
#pragma unroll
    for (int c = 0; c < 32; c++) {
        float acc = 0.f;
#pragma unroll
        for (int d = 0; d < 32; d++) acc += Asm[c * 32 + d] * vreg[d];
        ob[c * SPX] = acc;
    }
}

// ---------------------------------------------------------------------------
extern "C" void kernel_launch(void* const* d_in, const int* in_sizes, int n_in,
                              void* d_out, int out_size)
{
    const float* x     = (const float*)d_in[0];
    const float* qkv_r = (const float*)d_in[1];
    const float* qkv_i = (const float*)d_in[2];
    const float* qkv_j = (const float*)d_in[3];
    const float* qkv_k = (const float*)d_in[4];
    const float* qkv_b = (const float*)d_in[5];
    const float* dw_r  = (const float*)d_in[6];
    const float* dw_i  = (const float*)d_in[7];
    const float* dw_j  = (const float*)d_in[8];
    const float* dw_k  = (const float*)d_in[9];
    const float* dw_b  = (const float*)d_in[10];
    const float* po_r  = (const float*)d_in[11];
    const float* po_i  = (const float*)d_in[12];
    const float* po_j  = (const float*)d_in[13];
    const float* po_k  = (const float*)d_in[14];
    const float* po_b  = (const float*)d_in[15];
    const float* temp  = (const float*)d_in[16];
    float* out = (float*)d_out;

    expand_small<<<288, 256>>>(qkv_r, qkv_i, qkv_j, qkv_k, po_r, po_i, po_j, po_k);
    expand_dw<<<5184, 256>>>(dw_r, dw_i, dw_j, dw_k);

    gemm1x1<<<dim3(6, 256, 2), 256>>>(0, x, nullptr, qkv_b);       // 1x1 qkv conv
    conv3x3<<<dim3(6, 256, 2), 256>>>(dw_b);                        // 3x3 conv
    norms_kernel<<<512, 256>>>();
    gram_kernel<<<1024, 256>>>();
    softmax_kernel<<<256, 32>>>(temp);
    attnv_kernel<<<512, 256>>>();
    gemm1x1<<<dim3(2, 256, 2), 256>>>(1, nullptr, out, po_b);       // 1x1 out conv
}

// round 3
// speedup vs baseline: 1.3323x; 1.3323x over previous
#include <cuda_runtime.h>
#include <cuda_bf16.h>

// ---------------------------------------------------------------------------
// QAttention — round 2: conv3x3 rewritten with packed fma.rn.f32x2 (FFMA2),
// 128x128 tiles, pre-shifted B copies, pre-duplicated A pairs in smem.
// ---------------------------------------------------------------------------

#define SPX 16384           // H*W
#define NB  2               // batch

// ------------------- device scratch (no allocations allowed) ----------------
__device__ float g_Wqkv[384 * 128];
__device__ float g_Wdw [9 * 384 * 384];   // [tap][ic][oc]  (transposed!)
__device__ float g_Wpo [128 * 128];
__device__ float g_y1  [NB * 384 * SPX];
__device__ float g_y2  [NB * 384 * SPX];
__device__ float g_ao  [NB * 128 * SPX];
__device__ float g_scale[NB * 256];       // [b][{q=0,k=1}*128 + ch]  inv-norms
__device__ float g_G   [NB * 4 * 1024];   // raw gram per (b,h): 32x32
__device__ float g_A   [NB * 4 * 1024];   // softmaxed attn

// Hamilton block table
__device__ __forceinline__ void ham(int bo, int bi, int& src, float& sgn) {
    const int   SRC[4][4] = {{0,1,2,3},{1,0,3,2},{2,3,0,1},{3,2,1,0}};
    const float SGN[4][4] = {{1.f,-1.f,-1.f,-1.f},
                             {1.f, 1.f,-1.f, 1.f},
                             {1.f, 1.f, 1.f,-1.f},
                             {1.f,-1.f, 1.f, 1.f}};
    src = SRC[bo][bi];
    sgn = SGN[bo][bi];
}

// ------------------- packed f32x2 helpers -----------------------------------
__device__ __forceinline__ void fma2(unsigned long long& d,
                                     unsigned long long a, unsigned long long b) {
    asm("fma.rn.f32x2 %0, %1, %2, %0;" : "+l"(d) : "l"(a), "l"(b));
}
__device__ __forceinline__ float2 unpk(unsigned long long v) {
    float2 r; asm("mov.b64 {%0,%1}, %2;" : "=f"(r.x), "=f"(r.y) : "l"(v)); return r;
}

// ------------------- weight expansion + G zero ------------------------------
__global__ void expand_small(const float* __restrict__ qr, const float* __restrict__ qi,
                             const float* __restrict__ qj, const float* __restrict__ qk,
                             const float* __restrict__ pr, const float* __restrict__ pi,
                             const float* __restrict__ pj, const float* __restrict__ pk)
{
    int t = blockIdx.x * 256 + threadIdx.x;
    if (t < 49152) {
        int oc = t >> 7, ic = t & 127;
        int bo = oc / 96, oo = oc - bo * 96;
        int bi = ic >> 5, ii = ic & 31;
        const float* srcs[4] = {qr, qi, qj, qk};
        int s; float sg; ham(bo, bi, s, sg);
        g_Wqkv[t] = sg * srcs[s][oo * 32 + ii];
    } else if (t < 65536) {
        int e = t - 49152;
        int oc = e >> 7, ic = e & 127;
        int bo = oc >> 5, oo = oc & 31;
        int bi = ic >> 5, ii = ic & 31;
        const float* srcs[4] = {pr, pi, pj, pk};
        int s; float sg; ham(bo, bi, s, sg);
        g_Wpo[e] = sg * srcs[s][oo * 32 + ii];
    } else {
        g_G[t - 65536] = 0.f;
    }
}

// [tap][ic][oc] layout: 5184 blocks x 256 thr
__global__ void expand_dw(const float* __restrict__ dr, const float* __restrict__ di,
                          const float* __restrict__ dj, const float* __restrict__ dk)
{
    int t = blockIdx.x * 256 + threadIdx.x;
    int oc  = t / 3456;
    int rem = t - oc * 3456;
    int ic  = rem / 9;
    int tap = rem - ic * 9;
    int bo = oc / 96, oo = oc - bo * 96;
    int bi = ic / 96, ii = ic - bi * 96;
    const float* srcs[4] = {dr, di, dj, dk};
    int s; float sg; ham(bo, bi, s, sg);
    g_Wdw[tap * 147456 + ic * 384 + oc] = sg * srcs[s][(oo * 96 + ii) * 9 + tap];
}

// ------------------- 1x1 conv GEMM (K=128) ----------------------------------
__global__ void gemm1x1(int mode, const float* __restrict__ Xin, float* __restrict__ Oout,
                        const float* __restrict__ bias)
{
    __shared__ __align__(16) float As[16][68];
    __shared__ __align__(16) float Bs[16][64];
    const float* W; const float* B; float* C; int cbs;
    if (mode == 0) { W = g_Wqkv; B = Xin;  C = g_y1; cbs = 384 * SPX; }
    else           { W = g_Wpo;  B = g_ao; C = Oout; cbs = 128 * SPX; }

    int b  = blockIdx.z;
    int m0 = blockIdx.x * 64, n0 = blockIdx.y * 64;
    int tid = threadIdx.x;
    int tx4 = (tid & 15) * 4, ty4 = (tid >> 4) * 4;
    int lm  = tid >> 2,  lk4 = (tid & 3) * 4;
    int lk  = tid >> 4,  ln4 = (tid & 15) * 4;
    const float* Bb = B + b * 128 * SPX;

    float acc[4][4];
#pragma unroll
    for (int i = 0; i < 4; i++)
#pragma unroll
        for (int j = 0; j < 4; j++) acc[i][j] = 0.f;

    for (int k0 = 0; k0 < 128; k0 += 16) {
        float4 a4 = *(const float4*)&W[(m0 + lm) * 128 + k0 + lk4];
        As[lk4 + 0][lm] = a4.x; As[lk4 + 1][lm] = a4.y;
        As[lk4 + 2][lm] = a4.z; As[lk4 + 3][lm] = a4.w;
        *(float4*)&Bs[lk][ln4] = *(const float4*)&Bb[(k0 + lk) * SPX + n0 + ln4];
        __syncthreads();
#pragma unroll
        for (int kk = 0; kk < 16; kk++) {
            float4 av = *(const float4*)&As[kk][ty4];
            float4 bv = *(const float4*)&Bs[kk][tx4];
            float a_[4] = {av.x, av.y, av.z, av.w};
            float b_[4] = {bv.x, bv.y, bv.z, bv.w};
#pragma unroll
            for (int i = 0; i < 4; i++)
#pragma unroll
                for (int j = 0; j < 4; j++) acc[i][j] += a_[i] * b_[j];
        }
        __syncthreads();
    }
    float* Cb = C + b * cbs;
#pragma unroll
    for (int i = 0; i < 4; i++) {
        float bs = bias[m0 + ty4 + i];
        float4 v = make_float4(acc[i][0] + bs, acc[i][1] + bs, acc[i][2] + bs, acc[i][3] + bs);
        *(float4*)&Cb[(m0 + ty4 + i) * SPX + n0 + tx4] = v;
    }
}

// ------------------- 3x3 conv: FFMA2, 128oc x 128px tiles --------------------
// grid (3 oc-tiles, 128 h, 2 b), 256 threads, 8x8 outputs/thread.
// smem: A duplicated pairs [wtap][kk][oc] (float2), B pre-shifted [dw][kk][w].
__global__ __launch_bounds__(256, 2) void conv3x3(const float* __restrict__ bias)
{
    __shared__ __align__(16) float2 Asd[3][8][128];   // 24 KB
    __shared__ __align__(16) float  Bs [3][8][128];   // 12 KB

    int b   = blockIdx.z;
    int oc0 = blockIdx.x * 128;
    int h   = blockIdx.y;
    int tid = threadIdx.x;
    int tx4 = (tid & 15) * 4;          // px group base (0..60)
    int ty8 = (tid >> 4) * 8;          // oc group base (0..120)
    int lkk = tid >> 5;                // loader: kk 0..7
    int lw4 = (tid & 31) * 4;          // loader: 0..124 (w or oc)
    const float* y1b = g_y1 + b * 384 * SPX;

    unsigned long long acc[8][4];
#pragma unroll
    for (int i = 0; i < 8; i++)
#pragma unroll
        for (int j = 0; j < 4; j++) acc[i][j] = 0ull;

    for (int dh = 0; dh < 3; dh++) {
        int hh = h + dh - 1;
        if ((unsigned)hh >= 128u) continue;          // uniform per block
        const float* Wd   = g_Wdw + dh * 3 * 147456;
        const float* rowp = y1b + hh * 128;

        for (int k0 = 0; k0 < 384; k0 += 8) {
            // --- load A: 3 w-taps, duplicated pairs ---
#pragma unroll
            for (int wt = 0; wt < 3; wt++) {
                float4 wv = *(const float4*)&Wd[wt * 147456 + (k0 + lkk) * 384 + oc0 + lw4];
                Asd[wt][lkk][lw4 + 0] = make_float2(wv.x, wv.x);
                Asd[wt][lkk][lw4 + 1] = make_float2(wv.y, wv.y);
                Asd[wt][lkk][lw4 + 2] = make_float2(wv.z, wv.z);
                Asd[wt][lkk][lw4 + 3] = make_float2(wv.w, wv.w);
            }
            // --- load B: center + two shifted copies (with conv zero-pad) ---
            {
                float4 v = *(const float4*)&rowp[(k0 + lkk) * SPX + lw4];
                *(float4*)&Bs[1][lkk][lw4] = v;
                // Bs[0][w] = in[w-1]
                Bs[0][lkk][lw4 + 1] = v.x;
                Bs[0][lkk][lw4 + 2] = v.y;
                Bs[0][lkk][lw4 + 3] = v.z;
                if (lw4 < 124) Bs[0][lkk][lw4 + 4] = v.w;
                else           Bs[0][lkk][0] = 0.f;
                // Bs[2][w] = in[w+1]
                if (lw4 > 0)   Bs[2][lkk][lw4 - 1] = v.x;
                Bs[2][lkk][lw4 + 0] = v.y;
                Bs[2][lkk][lw4 + 1] = v.z;
                Bs[2][lkk][lw4 + 2] = v.w;
                if (lw4 == 124) Bs[2][lkk][127] = 0.f;
            }
            __syncthreads();

#pragma unroll
            for (int kk = 0; kk < 8; kk++) {
                unsigned long long bb[3][4];
#pragma unroll
                for (int dw = 0; dw < 3; dw++) {
                    ulonglong2 p = *(const ulonglong2*)&Bs[dw][kk][tx4];
                    ulonglong2 q = *(const ulonglong2*)&Bs[dw][kk][64 + tx4];
                    bb[dw][0] = p.x; bb[dw][1] = p.y;
                    bb[dw][2] = q.x; bb[dw][3] = q.y;
                }
#pragma unroll
                for (int wt = 0; wt < 3; wt++) {
                    const ulonglong2* ap = (const ulonglong2*)&Asd[wt][kk][ty8];
                    ulonglong2 a01 = ap[0], a23 = ap[1], a45 = ap[2], a67 = ap[3];
                    unsigned long long av[8] = {a01.x, a01.y, a23.x, a23.y,
                                                a45.x, a45.y, a67.x, a67.y};
#pragma unroll
                    for (int i = 0; i < 8; i++) {
#pragma unroll
                        for (int j = 0; j < 4; j++)
                            fma2(acc[i][j], av[i], bb[wt][j]);
                    }
                }
            }
            __syncthreads();
        }
    }

    // --- epilogue ---
    float* outp = g_y2 + b * 384 * SPX + h * 128;
#pragma unroll
    for (int i = 0; i < 8; i++) {
        float bs = bias[oc0 + ty8 + i];
        float2 r0 = unpk(acc[i][0]), r1 = unpk(acc[i][1]);
        float2 r2 = unpk(acc[i][2]), r3 = unpk(acc[i][3]);
        float4 o0 = make_float4(r0.x + bs, r0.y + bs, r1.x + bs, r1.y + bs);
        float4 o1 = make_float4(r2.x + bs, r2.y + bs, r3.x + bs, r3.y + bs);
        float* orow = outp + (oc0 + ty8 + i) * SPX;
        *(float4*)&orow[tx4]      = o0;
        *(float4*)&orow[64 + tx4] = o1;
    }
}

// ------------------- inverse L2 norms for q,k -------------------------------
__global__ void norms_kernel()
{
    int bi_ = blockIdx.x;
    int ch = bi_ & 127, qk = (bi_ >> 7) & 1, b = bi_ >> 8;
    const float4* p = (const float4*)(g_y2 + b * 384 * SPX + (qk * 128 + ch) * SPX);
    float ss = 0.f;
    for (int i = threadIdx.x; i < 4096; i += 256) {
        float4 v = p[i];
        ss += v.x * v.x + v.y * v.y + v.z * v.z + v.w * v.w;
    }
    __shared__ float red[256];
    red[threadIdx.x] = ss;
    __syncthreads();
    for (int o = 128; o > 0; o >>= 1) {
        if (threadIdx.x < o) red[threadIdx.x] += red[threadIdx.x + o];
        __syncthreads();
    }
    if (threadIdx.x == 0) g_scale[bi_] = 1.f / fmaxf(sqrtf(red[0]), 1e-12f);
}

// ------------------- raw gram q k^T (s-split + atomics) ----------------------
__global__ void gram_kernel()
{
    __shared__ float Qs[32 * 129];
    __shared__ float Ks[32 * 129];
    int bi_ = blockIdx.x;
    int split = bi_ & 127;
    int h = (bi_ >> 7) & 3;
    int b = bi_ >> 9;
    int s0 = split * 128;
    const float* gQ = g_y2 + b * 384 * SPX + (h * 32) * SPX + s0;
    const float* gK = gQ + 128 * SPX;
    int tid = threadIdx.x;
    for (int idx = tid; idx < 4096; idx += 256) {
        int row = idx >> 7, col = idx & 127;
        Qs[row * 129 + col] = gQ[row * SPX + col];
        Ks[row * 129 + col] = gK[row * SPX + col];
    }
    __syncthreads();
    int c = tid >> 3, d0 = (tid & 7) * 4;
    float a0 = 0.f, a1 = 0.f, a2 = 0.f, a3 = 0.f;
    const float* qrow = &Qs[c * 129];
#pragma unroll 4
    for (int s = 0; s < 128; s++) {
        float qv = qrow[s];
        a0 += qv * Ks[(d0 + 0) * 129 + s];
        a1 += qv * Ks[(d0 + 1) * 129 + s];
        a2 += qv * Ks[(d0 + 2) * 129 + s];
        a3 += qv * Ks[(d0 + 3) * 129 + s];
    }
    float* Gp = &g_G[(b * 4 + h) * 1024 + c * 32 + d0];
    atomicAdd(Gp + 0, a0); atomicAdd(Gp + 1, a1);
    atomicAdd(Gp + 2, a2); atomicAdd(Gp + 3, a3);
}

// ------------------- scale + softmax over d ---------------------------------
__global__ void softmax_kernel(const float* __restrict__ temp)
{
    int bi_ = blockIdx.x;
    int c = bi_ & 31;
    int bh = bi_ >> 5;
    int h = bh & 3, b = bh >> 2;
    int d = threadIdx.x;
    float g = g_G[bh * 1024 + c * 32 + d]
            * g_scale[b * 256 + h * 32 + c]
            * g_scale[b * 256 + 128 + h * 32 + d]
            * temp[h];
    float mx = g;
    for (int o = 16; o > 0; o >>= 1) mx = fmaxf(mx, __shfl_xor_sync(0xffffffffu, mx, o));
    float e = expf(g - mx);
    float sm = e;
    for (int o = 16; o > 0; o >>= 1) sm += __shfl_xor_sync(0xffffffffu, sm, o);
    g_A[bh * 1024 + c * 32 + d] = e / sm;
}

// ------------------- out = attn @ v ------------------------------------------
__global__ void attnv_kernel()
{
    __shared__ float Asm[1024];
    int bi_ = blockIdx.x;
    int st = bi_ & 63;
    int h = (bi_ >> 6) & 3;
    int b = bi_ >> 8;
    int tid = threadIdx.x;
    int bh = b * 4 + h;
    for (int idx = tid; idx < 1024; idx += 256) Asm[idx] = g_A[bh * 1024 + idx];
    __syncthreads();
    int s = st * 256 + tid;
    const float* vb = g_y2 + b * 384 * SPX + (256 + h * 32) * SPX + s;
    float vreg[32];
#pragma unroll
    for (int d = 0; d < 32; d++) vreg[d] = vb[d * SPX];
    float* ob = g_ao + b * 128 * SPX + (h * 32) * SPX + s;
#pragma unroll
    for (int c = 0; c < 32; c++) {
        float acc = 0.f;
#pragma unroll
        for (int d = 0; d < 32; d++) acc += Asm[c * 32 + d] * vreg[d];
        ob[c * SPX] = acc;
    }
}

// ---------------------------------------------------------------------------
extern "C" void kernel_launch(void* const* d_in, const int* in_sizes, int n_in,
                              void* d_out, int out_size)
{
    const float* x     = (const float*)d_in[0];
    const float* qkv_r = (const float*)d_in[1];
    const float* qkv_i = (const float*)d_in[2];
    const float* qkv_j = (const float*)d_in[3];
    const float* qkv_k = (const float*)d_in[4];
    const float* qkv_b = (const float*)d_in[5];
    const float* dw_r  = (const float*)d_in[6];
    const float* dw_i  = (const float*)d_in[7];
    const float* dw_j  = (const float*)d_in[8];
    const float* dw_k  = (const float*)d_in[9];
    const float* dw_b  = (const float*)d_in[10];
    const float* po_r  = (const float*)d_in[11];
    const float* po_i  = (const float*)d_in[12];
    const float* po_j  = (const float*)d_in[13];
    const float* po_k  = (const float*)d_in[14];
    const float* po_b  = (const float*)d_in[15];
    const float* temp  = (const float*)d_in[16];
    float* out = (float*)d_out;

    expand_small<<<288, 256>>>(qkv_r, qkv_i, qkv_j, qkv_k, po_r, po_i, po_j, po_k);
    expand_dw<<<5184, 256>>>(dw_r, dw_i, dw_j, dw_k);

    gemm1x1<<<dim3(6, 256, 2), 256>>>(0, x, nullptr, qkv_b);       // 1x1 qkv conv
    conv3x3<<<dim3(3, 128, 2), 256>>>(dw_b);                        // 3x3 conv (FFMA2)
    norms_kernel<<<512, 256>>>();
    gram_kernel<<<1024, 256>>>();
    softmax_kernel<<<256, 32>>>(temp);
    attnv_kernel<<<512, 256>>>();
    gemm1x1<<<dim3(2, 256, 2), 256>>>(1, nullptr, out, po_b);       // 1x1 out conv
}

// round 7
// speedup vs baseline: 2.7376x; 2.0548x over previous
#include <cuda_runtime.h>
#include <cuda_fp16.h>
#include <cuda_bf16.h>
#include <cstdint>

// ---------------------------------------------------------------------------
// QAttention — round 6: conv3x3 as implicit-GEMM on mma.sync (HMMA m16n8k16),
// fp16 3-term split (Whi*Xhi + Wlo*Xhi + Whi*Xlo), cp.async 3-stage pipeline.
// (tcgen05 is unavailable: harness compiles via compute_103 virtual arch.)
// ---------------------------------------------------------------------------

#define SPX 16384           // H*W
#define NB  2               // batch

// ------------------- device scratch (no allocations allowed) ----------------
__device__ float  g_Wqkv[384 * 128];
__device__ __half g_Wh[9 * 384 * 384];    // [tap][oc][ic] fp16 hi
__device__ __half g_Wl[9 * 384 * 384];    // [tap][oc][ic] fp16 lo
__device__ float  g_Wpo [128 * 128];
__device__ __half g_xh[NB * 130 * 130 * 384];  // padded channel-last act hi
__device__ __half g_xl[NB * 130 * 130 * 384];  // padded channel-last act lo
__device__ float  g_y2  [NB * 384 * SPX];
__device__ float  g_ao  [NB * 128 * SPX];
__device__ float  g_scale[NB * 256];
__device__ float  g_G   [NB * 4 * 1024];
__device__ float  g_A   [NB * 4 * 1024];

// Hamilton block table
__device__ __forceinline__ void ham(int bo, int bi, int& src, float& sgn) {
    const int   SRC[4][4] = {{0,1,2,3},{1,0,3,2},{2,3,0,1},{3,2,1,0}};
    const float SGN[4][4] = {{1.f,-1.f,-1.f,-1.f},
                             {1.f, 1.f,-1.f, 1.f},
                             {1.f, 1.f, 1.f,-1.f},
                             {1.f,-1.f, 1.f, 1.f}};
    src = SRC[bo][bi];
    sgn = SGN[bo][bi];
}

// ------------------- PTX helpers --------------------------------------------
__device__ __forceinline__ uint32_t smem_u32(const void* p) {
    uint32_t a;
    asm("{ .reg .u64 t; cvta.to.shared.u64 t, %1; cvt.u32.u64 %0, t; }"
        : "=r"(a) : "l"(p));
    return a;
}
__device__ __forceinline__ void cpa16(uint32_t dst, const void* src) {
    asm volatile("cp.async.cg.shared.global [%0], [%1], 16;" :: "r"(dst), "l"(src));
}
#define CP_COMMIT() asm volatile("cp.async.commit_group;" ::: "memory")
#define CP_WAIT2()  asm volatile("cp.async.wait_group 2;"  ::: "memory")

__device__ __forceinline__ void ldsm4(uint32_t a[4], uint32_t addr) {
    asm volatile("ldmatrix.sync.aligned.m8n8.x4.shared.b16 {%0,%1,%2,%3}, [%4];"
                 : "=r"(a[0]), "=r"(a[1]), "=r"(a[2]), "=r"(a[3]) : "r"(addr));
}
__device__ __forceinline__ void mma16816(float d[4], const uint32_t a[4],
                                         const uint32_t b[2]) {
    asm volatile(
        "mma.sync.aligned.m16n8k16.row.col.f32.f16.f16.f32 "
        "{%0,%1,%2,%3},{%4,%5,%6,%7},{%8,%9},{%0,%1,%2,%3};"
        : "+f"(d[0]), "+f"(d[1]), "+f"(d[2]), "+f"(d[3])
        : "r"(a[0]), "r"(a[1]), "r"(a[2]), "r"(a[3]), "r"(b[0]), "r"(b[1]));
}

// ------------------- weight expansion + G zero ------------------------------
__global__ void expand_small(const float* __restrict__ qr, const float* __restrict__ qi,
                             const float* __restrict__ qj, const float* __restrict__ qk,
                             const float* __restrict__ pr, const float* __restrict__ pi,
                             const float* __restrict__ pj, const float* __restrict__ pk)
{
    int t = blockIdx.x * 256 + threadIdx.x;
    if (t < 49152) {
        int oc = t >> 7, ic = t & 127;
        int bo = oc / 96, oo = oc - bo * 96;
        int bi = ic >> 5, ii = ic & 31;
        const float* srcs[4] = {qr, qi, qj, qk};
        int s; float sg; ham(bo, bi, s, sg);
        g_Wqkv[t] = sg * srcs[s][oo * 32 + ii];
    } else if (t < 65536) {
        int e = t - 49152;
        int oc = e >> 7, ic = e & 127;
        int bo = oc >> 5, oo = oc & 31;
        int bi = ic >> 5, ii = ic & 31;
        const float* srcs[4] = {pr, pi, pj, pk};
        int s; float sg; ham(bo, bi, s, sg);
        g_Wpo[e] = sg * srcs[s][oo * 32 + ii];
    } else {
        g_G[t - 65536] = 0.f;
    }
}

// [tap][oc][ic] hi/lo fp16: 5184 blocks x 256 thr
__global__ void expand_dw(const float* __restrict__ dr, const float* __restrict__ di,
                          const float* __restrict__ dj, const float* __restrict__ dk)
{
    int t = blockIdx.x * 256 + threadIdx.x;
    int oc  = t / 3456;
    int rem = t - oc * 3456;
    int ic  = rem / 9;
    int tap = rem - ic * 9;
    int bo = oc / 96, oo = oc - bo * 96;
    int bi = ic / 96, ii = ic - bi * 96;
    const float* srcs[4] = {dr, di, dj, dk};
    int s; float sg; ham(bo, bi, s, sg);
    float w = sg * srcs[s][(oo * 96 + ii) * 9 + tap];
    __half hi = __float2half(w);
    __half lo = __float2half(w - __half2float(hi));
    int idx = tap * 147456 + oc * 384 + ic;
    g_Wh[idx] = hi;
    g_Wl[idx] = lo;
}

// ------------------- zero the pad border of g_xh/g_xl ------------------------
__global__ void zero_pad()
{
    int bp = blockIdx.x;
    int b = bp >= 516; int e = bp - b * 516;
    int row, col;
    if (e < 130)      { row = 0;   col = e; }
    else if (e < 260) { row = 129; col = e - 130; }
    else { int e2 = e - 260; row = 1 + (e2 >> 1); col = (e2 & 1) ? 129 : 0; }
    size_t base = ((size_t)(b * 130 + row) * 130 + col) * 384;
    float2 z = make_float2(0.f, 0.f);
    *(float2*)((char*)g_xh + base * 2 + threadIdx.x * 8) = z;
    *(float2*)((char*)g_xl + base * 2 + threadIdx.x * 8) = z;
}

// ------------------- 1x1 conv GEMM (K=128) ----------------------------------
__global__ void gemm1x1(int mode, const float* __restrict__ Xin, float* __restrict__ Oout,
                        const float* __restrict__ bias)
{
    __shared__ __align__(16) float As[16][68];
    __shared__ __align__(16) float Bs[16][64];
    const float* W; const float* B;
    if (mode == 0) { W = g_Wqkv; B = Xin;  }
    else           { W = g_Wpo;  B = g_ao; }

    int b  = blockIdx.z;
    int m0 = blockIdx.x * 64, n0 = blockIdx.y * 64;
    int tid = threadIdx.x;
    int tx4 = (tid & 15) * 4, ty4 = (tid >> 4) * 4;
    int lm  = tid >> 2,  lk4 = (tid & 3) * 4;
    int lk  = tid >> 4,  ln4 = (tid & 15) * 4;
    const float* Bb = B + b * 128 * SPX;

    float acc[4][4];
#pragma unroll
    for (int i = 0; i < 4; i++)
#pragma unroll
        for (int j = 0; j < 4; j++) acc[i][j] = 0.f;

    for (int k0 = 0; k0 < 128; k0 += 16) {
        float4 a4 = *(const float4*)&W[(m0 + lm) * 128 + k0 + lk4];
        As[lk4 + 0][lm] = a4.x; As[lk4 + 1][lm] = a4.y;
        As[lk4 + 2][lm] = a4.z; As[lk4 + 3][lm] = a4.w;
        *(float4*)&Bs[lk][ln4] = *(const float4*)&Bb[(k0 + lk) * SPX + n0 + ln4];
        __syncthreads();
#pragma unroll
        for (int kk = 0; kk < 16; kk++) {
            float4 av = *(const float4*)&As[kk][ty4];
            float4 bv = *(const float4*)&Bs[kk][tx4];
            float a_[4] = {av.x, av.y, av.z, av.w};
            float b_[4] = {bv.x, bv.y, bv.z, bv.w};
#pragma unroll
            for (int i = 0; i < 4; i++)
#pragma unroll
                for (int j = 0; j < 4; j++) acc[i][j] += a_[i] * b_[j];
        }
        __syncthreads();
    }

    if (mode == 1) {
        float* Cb = Oout + b * 128 * SPX;
#pragma unroll
        for (int i = 0; i < 4; i++) {
            float bs = bias[m0 + ty4 + i];
            float4 v = make_float4(acc[i][0] + bs, acc[i][1] + bs,
                                   acc[i][2] + bs, acc[i][3] + bs);
            *(float4*)&Cb[(m0 + ty4 + i) * SPX + n0 + tx4] = v;
        }
    } else {
        int h = n0 >> 7, w0r = n0 & 127;
        size_t rowbase = ((size_t)(b * 130) + (h + 1)) * 130;
        float bs0 = bias[m0 + ty4 + 0], bs1 = bias[m0 + ty4 + 1];
        float bs2 = bias[m0 + ty4 + 2], bs3 = bias[m0 + ty4 + 3];
#pragma unroll
        for (int j = 0; j < 4; j++) {
            int w = w0r + tx4 + j;
            size_t px = (rowbase + (w + 1)) * 384 + (m0 + ty4);
            float v0 = acc[0][j] + bs0, v1 = acc[1][j] + bs1;
            float v2 = acc[2][j] + bs2, v3 = acc[3][j] + bs3;
            __half a0 = __float2half(v0), a1 = __float2half(v1);
            __half a2 = __float2half(v2), a3 = __float2half(v3);
            __half l0 = __float2half(v0 - __half2float(a0));
            __half l1 = __float2half(v1 - __half2float(a1));
            __half l2 = __float2half(v2 - __half2float(a2));
            __half l3 = __float2half(v3 - __half2float(a3));
            __half2* ph = (__half2*)&g_xh[px];
            ph[0] = __halves2half2(a0, a1); ph[1] = __halves2half2(a2, a3);
            __half2* pl = (__half2*)&g_xl[px];
            pl[0] = __halves2half2(l0, l1); pl[1] = __halves2half2(l2, l3);
        }
    }
}

// ------------------- 3x3 conv: HMMA implicit GEMM ----------------------------
#define STAGE_BYTES 61440
#define CONV_SMEM   (3 * STAGE_BYTES)

__device__ __forceinline__ void load_chunk(uint32_t sb, int chunk, int oc0,
                                           int h0, int b, int tid)
{
    int tap = chunk / 12;
    int k0  = (chunk - tap * 12) * 32;
    int dh  = tap / 3, dwd = tap - dh * 3;
#pragma unroll
    for (int i = 0; i < 12; i++) {
        int gid = tid + i * 256;
        if (i < 4) {
            int whichW = gid >> 9;
            int row = (gid >> 2) & 127;
            int q = gid & 3;
            const __half* src = (whichW ? g_Wl : g_Wh)
                + (size_t)(tap * 384 + oc0 + row) * 384 + k0 + q * 8;
            cpa16(sb + whichW * 10240 + row * 80 + q * 16, src);
        } else {
            int g2 = gid - 1024;
            int whichX = g2 >> 10;
            int row = (g2 >> 2) & 255;
            int q = g2 & 3;
            int h = h0 + (row >> 7), w = row & 127;
            const __half* src = (whichX ? g_xl : g_xh)
                + ((size_t)(b * 130 + h + dh) * 130 + w + dwd) * 384 + k0 + q * 8;
            cpa16(sb + 20480 + whichX * 20480 + row * 80 + q * 16, src);
        }
    }
}

__global__ __launch_bounds__(256, 1) void conv3x3_hmma(const float* __restrict__ bias)
{
    extern __shared__ char smem[];
    uint32_t smem_base = smem_u32(smem);
    int tid  = threadIdx.x;
    int lane = tid & 31, wid = tid >> 5;
    int oc0 = blockIdx.x * 128;
    int h0  = blockIdx.y * 2;
    int b   = blockIdx.z;

    int mw = (wid & 1) * 64;
    int nw = (wid >> 1) * 64;
    int r = lane & 7, j = lane >> 3;
    uint32_t aRow = (uint32_t)((j & 1) * 8 + r);
    uint32_t aK   = (uint32_t)((j >> 1) * 16);
    uint32_t bN   = (uint32_t)((j >> 1) * 8 + r);
    uint32_t bK   = (uint32_t)((j & 1) * 16);

    float acc[4][8][4];
#pragma unroll
    for (int mi = 0; mi < 4; mi++)
#pragma unroll
        for (int ni = 0; ni < 8; ni++)
#pragma unroll
            for (int e = 0; e < 4; e++) acc[mi][ni][e] = 0.f;

    load_chunk(smem_base + 0 * STAGE_BYTES, 0, oc0, h0, b, tid); CP_COMMIT();
    load_chunk(smem_base + 1 * STAGE_BYTES, 1, oc0, h0, b, tid); CP_COMMIT();
    load_chunk(smem_base + 2 * STAGE_BYTES, 2, oc0, h0, b, tid); CP_COMMIT();

    for (int it = 0; it < 108; it++) {
        int s = it % 3;
        CP_WAIT2();
        __syncthreads();
        uint32_t sb  = smem_base + s * STAGE_BYTES;
        uint32_t sWh = sb, sWl = sb + 10240, sXh = sb + 20480, sXl = sb + 40960;

#pragma unroll
        for (int kb = 0; kb < 64; kb += 32) {
            uint32_t bfr[8][2], ah[4][4], at[4][4], t4[4];
#pragma unroll
            for (int u = 0; u < 4; u++) {
                ldsm4(t4, sXh + (nw + u * 16 + bN) * 80 + kb + bK);
                bfr[2 * u][0] = t4[0]; bfr[2 * u][1] = t4[1];
                bfr[2 * u + 1][0] = t4[2]; bfr[2 * u + 1][1] = t4[3];
            }
#pragma unroll
            for (int mi = 0; mi < 4; mi++)
                ldsm4(ah[mi], sWh + (mw + mi * 16 + aRow) * 80 + kb + aK);
#pragma unroll
            for (int mi = 0; mi < 4; mi++)
#pragma unroll
                for (int ni = 0; ni < 8; ni++) mma16816(acc[mi][ni], ah[mi], bfr[ni]);
#pragma unroll
            for (int mi = 0; mi < 4; mi++)
                ldsm4(at[mi], sWl + (mw + mi * 16 + aRow) * 80 + kb + aK);
#pragma unroll
            for (int mi = 0; mi < 4; mi++)
#pragma unroll
                for (int ni = 0; ni < 8; ni++) mma16816(acc[mi][ni], at[mi], bfr[ni]);
#pragma unroll
            for (int u = 0; u < 4; u++) {
                ldsm4(t4, sXl + (nw + u * 16 + bN) * 80 + kb + bK);
                bfr[2 * u][0] = t4[0]; bfr[2 * u][1] = t4[1];
                bfr[2 * u + 1][0] = t4[2]; bfr[2 * u + 1][1] = t4[3];
            }
#pragma unroll
            for (int mi = 0; mi < 4; mi++)
#pragma unroll
                for (int ni = 0; ni < 8; ni++) mma16816(acc[mi][ni], ah[mi], bfr[ni]);
        }
        __syncthreads();
        if (it + 3 < 108) load_chunk(sb, it + 3, oc0, h0, b, tid);
        CP_COMMIT();   // empty group at tail keeps wait_group accounting valid
    }

    int g = lane >> 2, tg = lane & 3;
#pragma unroll
    for (int mi = 0; mi < 4; mi++) {
        int m = oc0 + mw + mi * 16 + g;
        float bs0 = bias[m], bs1 = bias[m + 8];
#pragma unroll
        for (int ni = 0; ni < 8; ni++) {
            int n = nw + ni * 8 + tg * 2;
            int h = h0 + (n >> 7), w = n & 127;
            float* p = g_y2 + ((size_t)b * 384 + m) * SPX + h * 128 + w;
            p[0] = acc[mi][ni][0] + bs0;
            p[1] = acc[mi][ni][1] + bs0;
            float* p2 = p + 8 * SPX;
            p2[0] = acc[mi][ni][2] + bs1;
            p2[1] = acc[mi][ni][3] + bs1;
        }
    }
}

// ------------------- inverse L2 norms for q,k -------------------------------
__global__ void norms_kernel()
{
    int bi_ = blockIdx.x;
    int ch = bi_ & 127, qk = (bi_ >> 7) & 1, b = bi_ >> 8;
    const float4* p = (const float4*)(g_y2 + b * 384 * SPX + (qk * 128 + ch) * SPX);
    float ss = 0.f;
    for (int i = threadIdx.x; i < 4096; i += 256) {
        float4 v = p[i];
        ss += v.x * v.x + v.y * v.y + v.z * v.z + v.w * v.w;
    }
    __shared__ float red[256];
    red[threadIdx.x] = ss;
    __syncthreads();
    for (int o = 128; o > 0; o >>= 1) {
        if (threadIdx.x < o) red[threadIdx.x] += red[threadIdx.x + o];
        __syncthreads();
    }
    if (threadIdx.x == 0) g_scale[bi_] = 1.f / fmaxf(sqrtf(red[0]), 1e-12f);
}

// ------------------- raw gram q k^T (s-split + atomics) ----------------------
__global__ void gram_kernel()
{
    __shared__ float Qs[32 * 129];
    __shared__ float Ks[32 * 129];
    int bi_ = blockIdx.x;
    int split = bi_ & 127;
    int h = (bi_ >> 7) & 3;
    int b = bi_ >> 9;
    int s0 = split * 128;
    const float* gQ = g_y2 + b * 384 * SPX + (h * 32) * SPX + s0;
    const float* gK = gQ + 128 * SPX;
    int tid = threadIdx.x;
    for (int idx = tid; idx < 4096; idx += 256) {
        int row = idx >> 7, col = idx & 127;
        Qs[row * 129 + col] = gQ[row * SPX + col];
        Ks[row * 129 + col] = gK[row * SPX + col];
    }
    __syncthreads();
    int c = tid >> 3, d0 = (tid & 7) * 4;
    float a0 = 0.f, a1 = 0.f, a2 = 0.f, a3 = 0.f;
    const float* qrow = &Qs[c * 129];
#pragma unroll 4
    for (int s = 0; s < 128; s++) {
        float qv = qrow[s];
        a0 += qv * Ks[(d0 + 0) * 129 + s];
        a1 += qv * Ks[(d0 + 1) * 129 + s];
        a2 += qv * Ks[(d0 + 2) * 129 + s];
        a3 += qv * Ks[(d0 + 3) * 129 + s];
    }
    float* Gp = &g_G[(b * 4 + h) * 1024 + c * 32 + d0];
    atomicAdd(Gp + 0, a0); atomicAdd(Gp + 1, a1);
    atomicAdd(Gp + 2, a2); atomicAdd(Gp + 3, a3);
}

// ------------------- scale + softmax over d ---------------------------------
__global__ void softmax_kernel(const float* __restrict__ temp)
{
    int bi_ = blockIdx.x;
    int c = bi_ & 31;
    int bh = bi_ >> 5;
    int h = bh & 3, b = bh >> 2;
    int d = threadIdx.x;
    float g = g_G[bh * 1024 + c * 32 + d]
            * g_scale[b * 256 + h * 32 + c]
            * g_scale[b * 256 + 128 + h * 32 + d]
            * temp[h];
    float mx = g;
    for (int o = 16; o > 0; o >>= 1) mx = fmaxf(mx, __shfl_xor_sync(0xffffffffu, mx, o));
    float e = expf(g - mx);
    float sm = e;
    for (int o = 16; o > 0; o >>= 1) sm += __shfl_xor_sync(0xffffffffu, sm, o);
    g_A[bh * 1024 + c * 32 + d] = e / sm;
}

// ------------------- out = attn @ v ------------------------------------------
__global__ void attnv_kernel()
{
    __shared__ float Asm[1024];
    int bi_ = blockIdx.x;
    int st = bi_ & 63;
    int h = (bi_ >> 6) & 3;
    int b = bi_ >> 8;
    int tid = threadIdx.x;
    int bh = b * 4 + h;
    for (int idx = tid; idx < 1024; idx += 256) Asm[idx] = g_A[bh * 1024 + idx];
    __syncthreads();
    int s = st * 256 + tid;
    const float* vb = g_y2 + b * 384 * SPX + (256 + h * 32) * SPX + s;
    float vreg[32];
#pragma unroll
    for (int d = 0; d < 32; d++) vreg[d] = vb[d * SPX];
    float* ob = g_ao + b * 128 * SPX + (h * 32) * SPX + s;
#pragma unroll
    for (int c = 0; c < 32; c++) {
        float acc = 0.f;
#pragma unroll
        for (int d = 0; d < 32; d++) acc += Asm[c * 32 + d] * vreg[d];
        ob[c * SPX] = acc;
    }
}

// ---------------------------------------------------------------------------
extern "C" void kernel_launch(void* const* d_in, const int* in_sizes, int n_in,
                              void* d_out, int out_size)
{
    const float* x     = (const float*)d_in[0];
    const float* qkv_r = (const float*)d_in[1];
    const float* qkv_i = (const float*)d_in[2];
    const float* qkv_j = (const float*)d_in[3];
    const float* qkv_k = (const float*)d_in[4];
    const float* qkv_b = (const float*)d_in[5];
    const float* dw_r  = (const float*)d_in[6];
    const float* dw_i  = (const float*)d_in[7];
    const float* dw_j  = (const float*)d_in[8];
    const float* dw_k  = (const float*)d_in[9];
    const float* dw_b  = (const float*)d_in[10];
    const float* po_r  = (const float*)d_in[11];
    const float* po_i  = (const float*)d_in[12];
    const float* po_j  = (const float*)d_in[13];
    const float* po_k  = (const float*)d_in[14];
    const float* po_b  = (const float*)d_in[15];
    const float* temp  = (const float*)d_in[16];
    float* out = (float*)d_out;

    cudaFuncSetAttribute(conv3x3_hmma, cudaFuncAttributeMaxDynamicSharedMemorySize,
                         CONV_SMEM);

    expand_small<<<288, 256>>>(qkv_r, qkv_i, qkv_j, qkv_k, po_r, po_i, po_j, po_k);
    expand_dw<<<5184, 256>>>(dw_r, dw_i, dw_j, dw_k);
    zero_pad<<<1032, 96>>>();

    gemm1x1<<<dim3(6, 256, 2), 256>>>(0, x, nullptr, qkv_b);        // 1x1 qkv conv
    conv3x3_hmma<<<dim3(3, 64, 2), 256, CONV_SMEM>>>(dw_b);         // 3x3 conv (HMMA)
    norms_kernel<<<512, 256>>>();
    gram_kernel<<<1024, 256>>>();
    softmax_kernel<<<256, 32>>>(temp);
    attnv_kernel<<<512, 256>>>();
    gemm1x1<<<dim3(2, 256, 2), 256>>>(1, nullptr, out, po_b);       // 1x1 out conv
}

// round 11
// speedup vs baseline: 2.9470x; 1.0765x over previous
#include <cuda_runtime.h>
#include <cuda_fp16.h>
#include <cuda_bf16.h>
#include <cstdint>

// ---------------------------------------------------------------------------
// QAttention — round 8: conv3x3 HMMA with X-reuse chunks (load X once per dh,
// 3 w-taps via smem row offsets; 36 iters, 2-stage 103KB pipeline) +
// gemm1x1 on packed fma.rn.f32x2.
// ---------------------------------------------------------------------------

#define SPX 16384           // H*W
#define NB  2               // batch

// ------------------- device scratch (no allocations allowed) ----------------
__device__ float  g_Wqkv[384 * 128];
__device__ __half g_Wh[9 * 384 * 384];    // [tap][oc][ic] fp16 hi
__device__ __half g_Wl[9 * 384 * 384];    // [tap][oc][ic] fp16 lo
__device__ float  g_Wpo [128 * 128];
__device__ __half g_xh[NB * 130 * 130 * 384];  // padded channel-last act hi
__device__ __half g_xl[NB * 130 * 130 * 384];  // padded channel-last act lo
__device__ float  g_y2  [NB * 384 * SPX];
__device__ float  g_ao  [NB * 128 * SPX];
__device__ float  g_scale[NB * 256];
__device__ float  g_G   [NB * 4 * 1024];
__device__ float  g_A   [NB * 4 * 1024];

// Hamilton block table
__device__ __forceinline__ void ham(int bo, int bi, int& src, float& sgn) {
    const int   SRC[4][4] = {{0,1,2,3},{1,0,3,2},{2,3,0,1},{3,2,1,0}};
    const float SGN[4][4] = {{1.f,-1.f,-1.f,-1.f},
                             {1.f, 1.f,-1.f, 1.f},
                             {1.f, 1.f, 1.f,-1.f},
                             {1.f,-1.f, 1.f, 1.f}};
    src = SRC[bo][bi];
    sgn = SGN[bo][bi];
}

// ------------------- PTX helpers --------------------------------------------
__device__ __forceinline__ uint32_t smem_u32(const void* p) {
    uint32_t a;
    asm("{ .reg .u64 t; cvta.to.shared.u64 t, %1; cvt.u32.u64 %0, t; }"
        : "=r"(a) : "l"(p));
    return a;
}
__device__ __forceinline__ void cpa16(uint32_t dst, const void* src) {
    asm volatile("cp.async.cg.shared.global [%0], [%1], 16;" :: "r"(dst), "l"(src));
}
#define CP_COMMIT() asm volatile("cp.async.commit_group;" ::: "memory")
#define CP_WAIT1()  asm volatile("cp.async.wait_group 1;"  ::: "memory")

__device__ __forceinline__ void ldsm4(uint32_t a[4], uint32_t addr) {
    asm volatile("ldmatrix.sync.aligned.m8n8.x4.shared.b16 {%0,%1,%2,%3}, [%4];"
                 : "=r"(a[0]), "=r"(a[1]), "=r"(a[2]), "=r"(a[3]) : "r"(addr));
}
__device__ __forceinline__ void mma16816(float d[4], const uint32_t a[4],
                                         const uint32_t b[2]) {
    asm volatile(
        "mma.sync.aligned.m16n8k16.row.col.f32.f16.f16.f32 "
        "{%0,%1,%2,%3},{%4,%5,%6,%7},{%8,%9},{%0,%1,%2,%3};"
        : "+f"(d[0]), "+f"(d[1]), "+f"(d[2]), "+f"(d[3])
        : "r"(a[0]), "r"(a[1]), "r"(a[2]), "r"(a[3]), "r"(b[0]), "r"(b[1]));
}
// packed f32x2
__device__ __forceinline__ void fma2(unsigned long long& d,
                                     unsigned long long a, unsigned long long b) {
    asm("fma.rn.f32x2 %0, %1, %2, %0;" : "+l"(d) : "l"(a), "l"(b));
}
__device__ __forceinline__ float2 unpk(unsigned long long v) {
    float2 r; asm("mov.b64 {%0,%1}, %2;" : "=f"(r.x), "=f"(r.y) : "l"(v)); return r;
}

// ------------------- weight expansion + G zero ------------------------------
__global__ void expand_small(const float* __restrict__ qr, const float* __restrict__ qi,
                             const float* __restrict__ qj, const float* __restrict__ qk,
                             const float* __restrict__ pr, const float* __restrict__ pi,
                             const float* __restrict__ pj, const float* __restrict__ pk)
{
    int t = blockIdx.x * 256 + threadIdx.x;
    if (t < 49152) {
        int oc = t >> 7, ic = t & 127;
        int bo = oc / 96, oo = oc - bo * 96;
        int bi = ic >> 5, ii = ic & 31;
        const float* srcs[4] = {qr, qi, qj, qk};
        int s; float sg; ham(bo, bi, s, sg);
        g_Wqkv[t] = sg * srcs[s][oo * 32 + ii];
    } else if (t < 65536) {
        int e = t - 49152;
        int oc = e >> 7, ic = e & 127;
        int bo = oc >> 5, oo = oc & 31;
        int bi = ic >> 5, ii = ic & 31;
        const float* srcs[4] = {pr, pi, pj, pk};
        int s; float sg; ham(bo, bi, s, sg);
        g_Wpo[e] = sg * srcs[s][oo * 32 + ii];
    } else {
        g_G[t - 65536] = 0.f;
    }
}

// [tap][oc][ic] hi/lo fp16: 5184 blocks x 256 thr
__global__ void expand_dw(const float* __restrict__ dr, const float* __restrict__ di,
                          const float* __restrict__ dj, const float* __restrict__ dk)
{
    int t = blockIdx.x * 256 + threadIdx.x;
    int oc  = t / 3456;
    int rem = t - oc * 3456;
    int ic  = rem / 9;
    int tap = rem - ic * 9;
    int bo = oc / 96, oo = oc - bo * 96;
    int bi = ic / 96, ii = ic - bi * 96;
    const float* srcs[4] = {dr, di, dj, dk};
    int s; float sg; ham(bo, bi, s, sg);
    float w = sg * srcs[s][(oo * 96 + ii) * 9 + tap];
    __half hi = __float2half(w);
    __half lo = __float2half(w - __half2float(hi));
    int idx = tap * 147456 + oc * 384 + ic;
    g_Wh[idx] = hi;
    g_Wl[idx] = lo;
}

// ------------------- zero the pad border of g_xh/g_xl ------------------------
__global__ void zero_pad()
{
    int bp = blockIdx.x;
    int b = bp >= 516; int e = bp - b * 516;
    int row, col;
    if (e < 130)      { row = 0;   col = e; }
    else if (e < 260) { row = 129; col = e - 130; }
    else { int e2 = e - 260; row = 1 + (e2 >> 1); col = (e2 & 1) ? 129 : 0; }
    size_t base = ((size_t)(b * 130 + row) * 130 + col) * 384;
    float2 z = make_float2(0.f, 0.f);
    *(float2*)((char*)g_xh + base * 2 + threadIdx.x * 8) = z;
    *(float2*)((char*)g_xl + base * 2 + threadIdx.x * 8) = z;
}

// ------------------- 1x1 conv GEMM (K=128), FFMA2 inner loop -----------------
__global__ void gemm1x1(int mode, const float* __restrict__ Xin, float* __restrict__ Oout,
                        const float* __restrict__ bias)
{
    __shared__ __align__(16) float2 As2[16][66];
    __shared__ __align__(16) float  Bs[16][64];
    const float* W; const float* B;
    if (mode == 0) { W = g_Wqkv; B = Xin;  }
    else           { W = g_Wpo;  B = g_ao; }

    int b  = blockIdx.z;
    int m0 = blockIdx.x * 64, n0 = blockIdx.y * 64;
    int tid = threadIdx.x;
    int tx4 = (tid & 15) * 4, ty4 = (tid >> 4) * 4;
    int lm  = tid >> 2,  lk4 = (tid & 3) * 4;
    int lk  = tid >> 4,  ln4 = (tid & 15) * 4;
    const float* Bb = B + b * 128 * SPX;

    unsigned long long acc2[4][2];
#pragma unroll
    for (int i = 0; i < 4; i++) { acc2[i][0] = 0ull; acc2[i][1] = 0ull; }

    for (int k0 = 0; k0 < 128; k0 += 16) {
        float4 a4 = *(const float4*)&W[(m0 + lm) * 128 + k0 + lk4];
        As2[lk4 + 0][lm] = make_float2(a4.x, a4.x);
        As2[lk4 + 1][lm] = make_float2(a4.y, a4.y);
        As2[lk4 + 2][lm] = make_float2(a4.z, a4.z);
        As2[lk4 + 3][lm] = make_float2(a4.w, a4.w);
        *(float4*)&Bs[lk][ln4] = *(const float4*)&Bb[(k0 + lk) * SPX + n0 + ln4];
        __syncthreads();
#pragma unroll
        for (int kk = 0; kk < 16; kk++) {
            ulonglong2 bp = *(const ulonglong2*)&Bs[kk][tx4];
#pragma unroll
            for (int i = 0; i < 4; i++) {
                unsigned long long av = *(const unsigned long long*)&As2[kk][ty4 + i];
                fma2(acc2[i][0], av, bp.x);
                fma2(acc2[i][1], av, bp.y);
            }
        }
        __syncthreads();
    }

    if (mode == 1) {
        float* Cb = Oout + b * 128 * SPX;
#pragma unroll
        for (int i = 0; i < 4; i++) {
            float bs = bias[m0 + ty4 + i];
            float2 r0 = unpk(acc2[i][0]), r1 = unpk(acc2[i][1]);
            float4 v = make_float4(r0.x + bs, r0.y + bs, r1.x + bs, r1.y + bs);
            *(float4*)&Cb[(m0 + ty4 + i) * SPX + n0 + tx4] = v;
        }
    } else {
        int h = n0 >> 7, w0r = n0 & 127;
        size_t rowbase = ((size_t)(b * 130) + (h + 1)) * 130;
        float av[4][4];
#pragma unroll
        for (int i = 0; i < 4; i++) {
            float bs = bias[m0 + ty4 + i];
            float2 r0 = unpk(acc2[i][0]), r1 = unpk(acc2[i][1]);
            av[i][0] = r0.x + bs; av[i][1] = r0.y + bs;
            av[i][2] = r1.x + bs; av[i][3] = r1.y + bs;
        }
#pragma unroll
        for (int j = 0; j < 4; j++) {
            int w = w0r + tx4 + j;
            size_t px = (rowbase + (w + 1)) * 384 + (m0 + ty4);
            float v0 = av[0][j], v1 = av[1][j], v2 = av[2][j], v3 = av[3][j];
            __half a0 = __float2half(v0), a1 = __float2half(v1);
            __half a2 = __float2half(v2), a3 = __float2half(v3);
            __half l0 = __float2half(v0 - __half2float(a0));
            __half l1 = __float2half(v1 - __half2float(a1));
            __half l2 = __float2half(v2 - __half2float(a2));
            __half l3 = __float2half(v3 - __half2float(a3));
            __half2* ph = (__half2*)&g_xh[px];
            ph[0] = __halves2half2(a0, a1); ph[1] = __halves2half2(a2, a3);
            __half2* pl = (__half2*)&g_xl[px];
            pl[0] = __halves2half2(l0, l1); pl[1] = __halves2half2(l2, l3);
        }
    }
}

// ------------------- 3x3 conv: HMMA implicit GEMM with X-reuse ---------------
// CTA: M=128 oc x N=256 px (2 h rows). Chunk = (dh, 32-ic block): 36 chunks.
// Per chunk: W for 3 w-taps (hi/lo) + X strip of 260 padded rows (hi/lo).
// The 3 w-taps reuse the X strip via smem row offsets +0/+1/+2.
// Stage: W 6*128 rows + X 2*260 rows, 80B pitch rows of 32 ic fp16.
#define W_BYTES   61440              // 6*128*80
#define X_BYTES   41600              // 2*260*80
#define ST2_BYTES (W_BYTES + X_BYTES)   // 103040
#define CONV_SMEM (2 * ST2_BYTES)       // 206080

__device__ __forceinline__ void load_chunk2(uint32_t sb, int chunk, int oc0,
                                            int h0, int b, int tid)
{
    int dh = chunk / 12;
    int k0 = (chunk - dh * 12) * 32;
    // W: 6 tiles (wt*2+hl) x 128 rows x 4 quads = 3072 16B ops
#pragma unroll
    for (int i = 0; i < 12; i++) {
        int gid  = tid + i * 256;
        int comb = gid >> 9;              // 0..5 = wt*2+hl
        int wt   = comb >> 1, hl = comb & 1;
        int row  = (gid >> 2) & 127;
        int q    = gid & 3;
        const __half* src = (hl ? g_Wl : g_Wh)
            + (size_t)((dh * 3 + wt) * 384 + oc0 + row) * 384 + k0 + q * 8;
        cpa16(sb + (uint32_t)(comb * 128 + row) * 80 + q * 16, src);
    }
    // X: 2 (hi,lo) x 260 rows x 4 quads = 2080 16B ops
#pragma unroll
    for (int i = 0; i < 9; i++) {
        int gid = tid + i * 256;
        if (gid < 2080) {
            int hl = gid >= 1040;
            int g2 = gid - hl * 1040;
            int row = g2 >> 2, q = g2 & 3;
            int hsub = row >= 130;
            int px = row - hsub * 130;
            const __half* src = (hl ? g_xl : g_xh)
                + ((size_t)(b * 130 + h0 + hsub + dh) * 130 + px) * 384 + k0 + q * 8;
            cpa16(sb + W_BYTES + (uint32_t)(hl * 260 + row) * 80 + q * 16, src);
        }
    }
}

__global__ __launch_bounds__(256, 1) void conv3x3_hmma(const float* __restrict__ bias)
{
    extern __shared__ char smem[];
    uint32_t sb0 = smem_u32(smem);
    int tid  = threadIdx.x;
    int lane = tid & 31, wid = tid >> 5;
    int oc0 = blockIdx.x * 128;
    int h0  = blockIdx.y * 2;
    int b   = blockIdx.z;

    int mw = (wid & 1) * 64;
    int nw = (wid >> 1) * 64;
    int r = lane & 7, j = lane >> 3;
    uint32_t aRow = (uint32_t)((j & 1) * 8 + r);
    uint32_t aK   = (uint32_t)((j >> 1) * 16);
    uint32_t bN   = (uint32_t)((j >> 1) * 8 + r);
    uint32_t bK   = (uint32_t)((j & 1) * 16);
    int hsub  = nw >> 7;          // which h row this warp covers
    int wbase = nw & 127;

    float acc[4][8][4];
#pragma unroll
    for (int mi = 0; mi < 4; mi++)
#pragma unroll
        for (int ni = 0; ni < 8; ni++)
#pragma unroll
            for (int e = 0; e < 4; e++) acc[mi][ni][e] = 0.f;

    load_chunk2(sb0,             0, oc0, h0, b, tid); CP_COMMIT();
    load_chunk2(sb0 + ST2_BYTES, 1, oc0, h0, b, tid); CP_COMMIT();

    for (int it = 0; it < 36; it++) {
        uint32_t sb = sb0 + (uint32_t)(it & 1) * ST2_BYTES;
        CP_WAIT1();
        __syncthreads();
        uint32_t sW = sb, sX = sb + W_BYTES;

#pragma unroll
        for (int wt = 0; wt < 3; wt++) {
            uint32_t xrow = (uint32_t)(hsub * 130 + wbase + wt);
#pragma unroll
            for (int kb = 0; kb < 64; kb += 32) {
                uint32_t bhi[8][2], blo[8][2], af[4][4], t4[4];
                // B hi fragments (Xhi strip)
#pragma unroll
                for (int u = 0; u < 4; u++) {
                    ldsm4(t4, sX + (xrow + u * 16 + bN) * 80 + kb + bK);
                    bhi[2 * u][0] = t4[0]; bhi[2 * u][1] = t4[1];
                    bhi[2 * u + 1][0] = t4[2]; bhi[2 * u + 1][1] = t4[3];
                }
                // B lo fragments (Xlo strip)
#pragma unroll
                for (int u = 0; u < 4; u++) {
                    ldsm4(t4, sX + (260 + xrow + u * 16 + bN) * 80 + kb + bK);
                    blo[2 * u][0] = t4[0]; blo[2 * u][1] = t4[1];
                    blo[2 * u + 1][0] = t4[2]; blo[2 * u + 1][1] = t4[3];
                }
                // A hi; pass1 Whi*Xhi, pass2 Whi*Xlo
#pragma unroll
                for (int mi = 0; mi < 4; mi++)
                    ldsm4(af[mi], sW + ((wt * 2 + 0) * 128 + mw + mi * 16 + aRow) * 80
                                     + kb + aK);
#pragma unroll
                for (int mi = 0; mi < 4; mi++)
#pragma unroll
                    for (int ni = 0; ni < 8; ni++) mma16816(acc[mi][ni], af[mi], bhi[ni]);
#pragma unroll
                for (int mi = 0; mi < 4; mi++)
#pragma unroll
                    for (int ni = 0; ni < 8; ni++) mma16816(acc[mi][ni], af[mi], blo[ni]);
                // A lo; pass3 Wlo*Xhi
#pragma unroll
                for (int mi = 0; mi < 4; mi++)
                    ldsm4(af[mi], sW + ((wt * 2 + 1) * 128 + mw + mi * 16 + aRow) * 80
                                     + kb + aK);
#pragma unroll
                for (int mi = 0; mi < 4; mi++)
#pragma unroll
                    for (int ni = 0; ni < 8; ni++) mma16816(acc[mi][ni], af[mi], bhi[ni]);
            }
        }
        __syncthreads();
        if (it + 2 < 36) load_chunk2(sb, it + 2, oc0, h0, b, tid);
        CP_COMMIT();   // empty group at tail keeps wait_group accounting valid
    }

    // epilogue: acc -> g_y2 (+bias)
    int g = lane >> 2, tg = lane & 3;
#pragma unroll
    for (int mi = 0; mi < 4; mi++) {
        int m = oc0 + mw + mi * 16 + g;
        float bs0 = bias[m], bs1 = bias[m + 8];
#pragma unroll
        for (int ni = 0; ni < 8; ni++) {
            int n = nw + ni * 8 + tg * 2;
            int h = h0 + (n >> 7), w = n & 127;
            float* p = g_y2 + ((size_t)b * 384 + m) * SPX + h * 128 + w;
            p[0] = acc[mi][ni][0] + bs0;
            p[1] = acc[mi][ni][1] + bs0;
            float* p2 = p + 8 * SPX;
            p2[0] = acc[mi][ni][2] + bs1;
            p2[1] = acc[mi][ni][3] + bs1;
        }
    }
}

// ------------------- inverse L2 norms for q,k -------------------------------
__global__ void norms_kernel()
{
    int bi_ = blockIdx.x;
    int ch = bi_ & 127, qk = (bi_ >> 7) & 1, b = bi_ >> 8;
    const float4* p = (const float4*)(g_y2 + b * 384 * SPX + (qk * 128 + ch) * SPX);
    float ss = 0.f;
    for (int i = threadIdx.x; i < 4096; i += 256) {
        float4 v = p[i];
        ss += v.x * v.x + v.y * v.y + v.z * v.z + v.w * v.w;
    }
    __shared__ float red[256];
    red[threadIdx.x] = ss;
    __syncthreads();
    for (int o = 128; o > 0; o >>= 1) {
        if (threadIdx.x < o) red[threadIdx.x] += red[threadIdx.x + o];
        __syncthreads();
    }
    if (threadIdx.x == 0) g_scale[bi_] = 1.f / fmaxf(sqrtf(red[0]), 1e-12f);
}

// ------------------- raw gram q k^T (s-split + atomics) ----------------------
__global__ void gram_kernel()
{
    __shared__ float Qs[32 * 129];
    __shared__ float Ks[32 * 129];
    int bi_ = blockIdx.x;
    int split = bi_ & 127;
    int h = (bi_ >> 7) & 3;
    int b = bi_ >> 9;
    int s0 = split * 128;
    const float* gQ = g_y2 + b * 384 * SPX + (h * 32) * SPX + s0;
    const float* gK = gQ + 128 * SPX;
    int tid = threadIdx.x;
    for (int idx = tid; idx < 4096; idx += 256) {
        int row = idx >> 7, col = idx & 127;
        Qs[row * 129 + col] = gQ[row * SPX + col];
        Ks[row * 129 + col] = gK[row * SPX + col];
    }
    __syncthreads();
    int c = tid >> 3, d0 = (tid & 7) * 4;
    float a0 = 0.f, a1 = 0.f, a2 = 0.f, a3 = 0.f;
    const float* qrow = &Qs[c * 129];
#pragma unroll 4
    for (int s = 0; s < 128; s++) {
        float qv = qrow[s];
        a0 += qv * Ks[(d0 + 0) * 129 + s];
        a1 += qv * Ks[(d0 + 1) * 129 + s];
        a2 += qv * Ks[(d0 + 2) * 129 + s];
        a3 += qv * Ks[(d0 + 3) * 129 + s];
    }
    float* Gp = &g_G[(b * 4 + h) * 1024 + c * 32 + d0];
    atomicAdd(Gp + 0, a0); atomicAdd(Gp + 1, a1);
    atomicAdd(Gp + 2, a2); atomicAdd(Gp + 3, a3);
}

// ------------------- scale + softmax over d ---------------------------------
__global__ void softmax_kernel(const float* __restrict__ temp)
{
    int bi_ = blockIdx.x;
    int c = bi_ & 31;
    int bh = bi_ >> 5;
    int h = bh & 3, b = bh >> 2;
    int d = threadIdx.x;
    float g = g_G[bh * 1024 + c * 32 + d]
            * g_scale[b * 256 + h * 32 + c]
            * g_scale[b * 256 + 128 + h * 32 + d]
            * temp[h];
    float mx = g;
    for (int o = 16; o > 0; o >>= 1) mx = fmaxf(mx, __shfl_xor_sync(0xffffffffu, mx, o));
    float e = expf(g - mx);
    float sm = e;
    for (int o = 16; o > 0; o >>= 1) sm += __shfl_xor_sync(0xffffffffu, sm, o);
    g_A[bh * 1024 + c * 32 + d] = e / sm;
}

// ------------------- out = attn @ v ------------------------------------------
__global__ void attnv_kernel()
{
    __shared__ float Asm[1024];
    int bi_ = blockIdx.x;
    int st = bi_ & 63;
    int h = (bi_ >> 6) & 3;
    int b = bi_ >> 8;
    int tid = threadIdx.x;
    int bh = b * 4 + h;
    for (int idx = tid; idx < 1024; idx += 256) Asm[idx] = g_A[bh * 1024 + idx];
    __syncthreads();
    int s = st * 256 + tid;
    const float* vb = g_y2 + b * 384 * SPX + (256 + h * 32) * SPX + s;
    float vreg[32];
#pragma unroll
    for (int d = 0; d < 32; d++) vreg[d] = vb[d * SPX];
    float* ob = g_ao + b * 128 * SPX + (h * 32) * SPX + s;
#pragma unroll
    for (int c = 0; c < 32; c++) {
        float acc = 0.f;
#pragma unroll
        for (int d = 0; d < 32; d++) acc += Asm[c * 32 + d] * vreg[d];
        ob[c * SPX] = acc;
    }
}

// ---------------------------------------------------------------------------
extern "C" void kernel_launch(void* const* d_in, const int* in_sizes, int n_in,
                              void* d_out, int out_size)
{
    const float* x     = (const float*)d_in[0];
    const float* qkv_r = (const float*)d_in[1];
    const float* qkv_i = (const float*)d_in[2];
    const float* qkv_j = (const float*)d_in[3];
    const float* qkv_k = (const float*)d_in[4];
    const float* qkv_b = (const float*)d_in[5];
    const float* dw_r  = (const float*)d_in[6];
    const float* dw_i  = (const float*)d_in[7];
    const float* dw_j  = (const float*)d_in[8];
    const float* dw_k  = (const float*)d_in[9];
    const float* dw_b  = (const float*)d_in[10];
    const float* po_r  = (const float*)d_in[11];
    const float* po_i  = (const float*)d_in[12];
    const float* po_j  = (const float*)d_in[13];
    const float* po_k  = (const float*)d_in[14];
    const float* po_b  = (const float*)d_in[15];
    const float* temp  = (const float*)d_in[16];
    float* out = (float*)d_out;

    cudaFuncSetAttribute(conv3x3_hmma, cudaFuncAttributeMaxDynamicSharedMemorySize,
                         CONV_SMEM);

    expand_small<<<288, 256>>>(qkv_r, qkv_i, qkv_j, qkv_k, po_r, po_i, po_j, po_k);
    expand_dw<<<5184, 256>>>(dw_r, dw_i, dw_j, dw_k);
    zero_pad<<<1032, 96>>>();

    gemm1x1<<<dim3(6, 256, 2), 256>>>(0, x, nullptr, qkv_b);        // 1x1 qkv conv
    conv3x3_hmma<<<dim3(3, 64, 2), 256, CONV_SMEM>>>(dw_b);         // 3x3 conv (HMMA)
    norms_kernel<<<512, 256>>>();
    gram_kernel<<<1024, 256>>>();
    softmax_kernel<<<256, 32>>>(temp);
    attnv_kernel<<<512, 256>>>();
    gemm1x1<<<dim3(2, 256, 2), 256>>>(1, nullptr, out, po_b);       // 1x1 out conv
}

// round 14
// speedup vs baseline: 3.8833x; 1.3177x over previous
#include <cuda_runtime.h>
#include <cuda_fp16.h>
#include <cuda_bf16.h>
#include <cstdint>

// ---------------------------------------------------------------------------
// QAttention — round 12:
//  * conv3x3 HMMA, 2-term fp16 split ((Whi+Wlo)*Xhi), X-reuse chunks
//  * attention folded into output 1x1 conv:  M = Wpo @ A  (per batch), out = M@v
//  * gemm1x1 FFMA2 with vectorized A loads
// ---------------------------------------------------------------------------

#define SPX 16384           // H*W
#define NB  2               // batch

// ------------------- device scratch (no allocations allowed) ----------------
__device__ float  g_Wqkv[384 * 128];
__device__ __half g_Wh[9 * 384 * 384];    // [tap][oc][ic] fp16 hi
__device__ __half g_Wl[9 * 384 * 384];    // [tap][oc][ic] fp16 lo
__device__ float  g_Wpo [128 * 128];
__device__ float  g_M   [NB * 128 * 128]; // folded Wpo @ attn
__device__ __half g_xh[NB * 130 * 130 * 384];  // padded channel-last act hi
__device__ float  g_y2  [NB * 384 * SPX];
__device__ float  g_scale[NB * 256];
__device__ float  g_G   [NB * 4 * 1024];
__device__ float  g_A   [NB * 4 * 1024];

// Hamilton block table
__device__ __forceinline__ void ham(int bo, int bi, int& src, float& sgn) {
    const int   SRC[4][4] = {{0,1,2,3},{1,0,3,2},{2,3,0,1},{3,2,1,0}};
    const float SGN[4][4] = {{1.f,-1.f,-1.f,-1.f},
                             {1.f, 1.f,-1.f, 1.f},
                             {1.f, 1.f, 1.f,-1.f},
                             {1.f,-1.f, 1.f, 1.f}};
    src = SRC[bo][bi];
    sgn = SGN[bo][bi];
}

// ------------------- PTX helpers --------------------------------------------
__device__ __forceinline__ uint32_t smem_u32(const void* p) {
    uint32_t a;
    asm("{ .reg .u64 t; cvta.to.shared.u64 t, %1; cvt.u32.u64 %0, t; }"
        : "=r"(a) : "l"(p));
    return a;
}
__device__ __forceinline__ void cpa16(uint32_t dst, const void* src) {
    asm volatile("cp.async.cg.shared.global [%0], [%1], 16;" :: "r"(dst), "l"(src));
}
#define CP_COMMIT() asm volatile("cp.async.commit_group;" ::: "memory")
#define CP_WAIT1()  asm volatile("cp.async.wait_group 1;"  ::: "memory")

__device__ __forceinline__ void ldsm4(uint32_t a[4], uint32_t addr) {
    asm volatile("ldmatrix.sync.aligned.m8n8.x4.shared.b16 {%0,%1,%2,%3}, [%4];"
                 : "=r"(a[0]), "=r"(a[1]), "=r"(a[2]), "=r"(a[3]) : "r"(addr));
}
__device__ __forceinline__ void mma16816(float d[4], const uint32_t a[4],
                                         const uint32_t b[2]) {
    asm volatile(
        "mma.sync.aligned.m16n8k16.row.col.f32.f16.f16.f32 "
        "{%0,%1,%2,%3},{%4,%5,%6,%7},{%8,%9},{%0,%1,%2,%3};"
        : "+f"(d[0]), "+f"(d[1]), "+f"(d[2]), "+f"(d[3])
        : "r"(a[0]), "r"(a[1]), "r"(a[2]), "r"(a[3]), "r"(b[0]), "r"(b[1]));
}
// packed f32x2
__device__ __forceinline__ void fma2(unsigned long long& d,
                                     unsigned long long a, unsigned long long b) {
    asm("fma.rn.f32x2 %0, %1, %2, %0;" : "+l"(d) : "l"(a), "l"(b));
}
__device__ __forceinline__ float2 unpk(unsigned long long v) {
    float2 r; asm("mov.b64 {%0,%1}, %2;" : "=f"(r.x), "=f"(r.y) : "l"(v)); return r;
}

// ------------------- weight expansion + G zero ------------------------------
__global__ void expand_small(const float* __restrict__ qr, const float* __restrict__ qi,
                             const float* __restrict__ qj, const float* __restrict__ qk,
                             const float* __restrict__ pr, const float* __restrict__ pi,
                             const float* __restrict__ pj, const float* __restrict__ pk)
{
    int t = blockIdx.x * 256 + threadIdx.x;
    if (t < 49152) {
        int oc = t >> 7, ic = t & 127;
        int bo = oc / 96, oo = oc - bo * 96;
        int bi = ic >> 5, ii = ic & 31;
        const float* srcs[4] = {qr, qi, qj, qk};
        int s; float sg; ham(bo, bi, s, sg);
        g_Wqkv[t] = sg * srcs[s][oo * 32 + ii];
    } else if (t < 65536) {
        int e = t - 49152;
        int oc = e >> 7, ic = e & 127;
        int bo = oc >> 5, oo = oc & 31;
        int bi = ic >> 5, ii = ic & 31;
        const float* srcs[4] = {pr, pi, pj, pk};
        int s; float sg; ham(bo, bi, s, sg);
        g_Wpo[e] = sg * srcs[s][oo * 32 + ii];
    } else {
        g_G[t - 65536] = 0.f;
    }
}

// [tap][oc][ic] hi/lo fp16: 5184 blocks x 256 thr
__global__ void expand_dw(const float* __restrict__ dr, const float* __restrict__ di,
                          const float* __restrict__ dj, const float* __restrict__ dk)
{
    int t = blockIdx.x * 256 + threadIdx.x;
    int oc  = t / 3456;
    int rem = t - oc * 3456;
    int ic  = rem / 9;
    int tap = rem - ic * 9;
    int bo = oc / 96, oo = oc - bo * 96;
    int bi = ic / 96, ii = ic - bi * 96;
    const float* srcs[4] = {dr, di, dj, dk};
    int s; float sg; ham(bo, bi, s, sg);
    float w = sg * srcs[s][(oo * 96 + ii) * 9 + tap];
    __half hi = __float2half(w);
    __half lo = __float2half(w - __half2float(hi));
    int idx = tap * 147456 + oc * 384 + ic;
    g_Wh[idx] = hi;
    g_Wl[idx] = lo;
}

// ------------------- zero the pad border of g_xh ------------------------------
__global__ void zero_pad()
{
    int bp = blockIdx.x;
    int b = bp >= 516; int e = bp - b * 516;
    int row, col;
    if (e < 130)      { row = 0;   col = e; }
    else if (e < 260) { row = 129; col = e - 130; }
    else { int e2 = e - 260; row = 1 + (e2 >> 1); col = (e2 & 1) ? 129 : 0; }
    size_t base = ((size_t)(b * 130 + row) * 130 + col) * 384;
    *(float2*)((char*)g_xh + base * 2 + threadIdx.x * 8) = make_float2(0.f, 0.f);
}

// ------------------- 1x1 conv GEMM (K=128), FFMA2 inner loop -----------------
// mode 0: W=g_Wqkv (M=384), B=x      -> padded channel-last fp16 hi
// mode 1: W=g_M[b] (M=128), B=v(y2)  -> d_out
__global__ void gemm1x1(int mode, const float* __restrict__ Xin, float* __restrict__ Oout,
                        const float* __restrict__ bias)
{
    __shared__ __align__(16) float2 As2[16][66];
    __shared__ __align__(16) float  Bs[16][64];
    int b  = blockIdx.z;
    const float* W; const float* Bb;
    if (mode == 0) { W = g_Wqkv;           Bb = Xin + (size_t)b * 128 * SPX; }
    else           { W = g_M + b * 16384;  Bb = g_y2 + (size_t)b * 384 * SPX + 256 * SPX; }

    int m0 = blockIdx.x * 64, n0 = blockIdx.y * 64;
    int tid = threadIdx.x;
    int tx4 = (tid & 15) * 4, ty4 = (tid >> 4) * 4;
    int lm  = tid >> 2,  lk4 = (tid & 3) * 4;
    int lk  = tid >> 4,  ln4 = (tid & 15) * 4;

    unsigned long long acc2[4][2];
#pragma unroll
    for (int i = 0; i < 4; i++) { acc2[i][0] = 0ull; acc2[i][1] = 0ull; }

    for (int k0 = 0; k0 < 128; k0 += 16) {
        float4 a4 = *(const float4*)&W[(m0 + lm) * 128 + k0 + lk4];
        As2[lk4 + 0][lm] = make_float2(a4.x, a4.x);
        As2[lk4 + 1][lm] = make_float2(a4.y, a4.y);
        As2[lk4 + 2][lm] = make_float2(a4.z, a4.z);
        As2[lk4 + 3][lm] = make_float2(a4.w, a4.w);
        *(float4*)&Bs[lk][ln4] = *(const float4*)&Bb[(size_t)(k0 + lk) * SPX + n0 + ln4];
        __syncthreads();
#pragma unroll
        for (int kk = 0; kk < 16; kk++) {
            ulonglong2 bp  = *(const ulonglong2*)&Bs[kk][tx4];
            ulonglong2 a01 = *(const ulonglong2*)&As2[kk][ty4];
            ulonglong2 a23 = *(const ulonglong2*)&As2[kk][ty4 + 2];
            fma2(acc2[0][0], a01.x, bp.x); fma2(acc2[0][1], a01.x, bp.y);
            fma2(acc2[1][0], a01.y, bp.x); fma2(acc2[1][1], a01.y, bp.y);
            fma2(acc2[2][0], a23.x, bp.x); fma2(acc2[2][1], a23.x, bp.y);
            fma2(acc2[3][0], a23.y, bp.x); fma2(acc2[3][1], a23.y, bp.y);
        }
        __syncthreads();
    }

    if (mode == 1) {
        float* Cb = Oout + (size_t)b * 128 * SPX;
#pragma unroll
        for (int i = 0; i < 4; i++) {
            float bs = bias[m0 + ty4 + i];
            float2 r0 = unpk(acc2[i][0]), r1 = unpk(acc2[i][1]);
            float4 v = make_float4(r0.x + bs, r0.y + bs, r1.x + bs, r1.y + bs);
            *(float4*)&Cb[(size_t)(m0 + ty4 + i) * SPX + n0 + tx4] = v;
        }
    } else {
        int h = n0 >> 7, w0r = n0 & 127;
        size_t rowbase = ((size_t)(b * 130) + (h + 1)) * 130;
        float av[4][4];
#pragma unroll
        for (int i = 0; i < 4; i++) {
            float bs = bias[m0 + ty4 + i];
            float2 r0 = unpk(acc2[i][0]), r1 = unpk(acc2[i][1]);
            av[i][0] = r0.x + bs; av[i][1] = r0.y + bs;
            av[i][2] = r1.x + bs; av[i][3] = r1.y + bs;
        }
#pragma unroll
        for (int j = 0; j < 4; j++) {
            int w = w0r + tx4 + j;
            size_t px = (rowbase + (w + 1)) * 384 + (m0 + ty4);
            __half2* ph = (__half2*)&g_xh[px];
            ph[0] = __halves2half2(__float2half(av[0][j]), __float2half(av[1][j]));
            ph[1] = __halves2half2(__float2half(av[2][j]), __float2half(av[3][j]));
        }
    }
}

// ------------------- 3x3 conv: HMMA implicit GEMM, 2-term split --------------
// CTA: M=128 oc x N=256 px (2 h rows). Chunk = (dh, 32-ic block): 36 chunks.
// W: 6 tiles (3 w-taps, hi/lo); X: one strip of 260 padded rows (hi only).
#define W_BYTES   61440              // 6*128*80
#define X_BYTES   20800              // 260*80
#define ST2_BYTES (W_BYTES + X_BYTES)   // 82240
#define CONV_SMEM (2 * ST2_BYTES)       // 164480

__device__ __forceinline__ void load_chunk2(uint32_t sb, int chunk, int oc0,
                                            int h0, int b, int tid)
{
    int dh = chunk / 12;
    int k0 = (chunk - dh * 12) * 32;
    // W: 6 tiles x 128 rows x 4 quads = 3072 16B ops
#pragma unroll
    for (int i = 0; i < 12; i++) {
        int gid  = tid + i * 256;
        int comb = gid >> 9;              // 0..5 = wt*2+hl
        int wt   = comb >> 1, hl = comb & 1;
        int row  = (gid >> 2) & 127;
        int q    = gid & 3;
        const __half* src = (hl ? g_Wl : g_Wh)
            + (size_t)((dh * 3 + wt) * 384 + oc0 + row) * 384 + k0 + q * 8;
        cpa16(sb + (uint32_t)(comb * 128 + row) * 80 + q * 16, src);
    }
    // X: 260 rows x 4 quads = 1040 16B ops
#pragma unroll
    for (int i = 0; i < 5; i++) {
        int gid = tid + i * 256;
        if (gid < 1040) {
            int row = gid >> 2, q = gid & 3;
            int hsub = row >= 130;
            int px = row - hsub * 130;
            const __half* src = g_xh
                + ((size_t)(b * 130 + h0 + hsub + dh) * 130 + px) * 384 + k0 + q * 8;
            cpa16(sb + W_BYTES + (uint32_t)row * 80 + q * 16, src);
        }
    }
}

__global__ __launch_bounds__(256, 1) void conv3x3_hmma(const float* __restrict__ bias)
{
    extern __shared__ char smem[];
    uint32_t sb0 = smem_u32(smem);
    int tid  = threadIdx.x;
    int lane = tid & 31, wid = tid >> 5;
    int oc0 = blockIdx.x * 128;
    int h0  = blockIdx.y * 2;
    int b   = blockIdx.z;

    int mw = (wid & 1) * 64;
    int nw = (wid >> 1) * 64;
    int r = lane & 7, j = lane >> 3;
    uint32_t aRow = (uint32_t)((j & 1) * 8 + r);
    uint32_t aK   = (uint32_t)((j >> 1) * 16);
    uint32_t bN   = (uint32_t)((j >> 1) * 8 + r);
    uint32_t bK   = (uint32_t)((j & 1) * 16);
    int hsub  = nw >> 7;          // which h row this warp covers
    int wbase = nw & 127;

    float acc[4][8][4];
#pragma unroll
    for (int mi = 0; mi < 4; mi++)
#pragma unroll
        for (int ni = 0; ni < 8; ni++)
#pragma unroll
            for (int e = 0; e < 4; e++) acc[mi][ni][e] = 0.f;

    load_chunk2(sb0,             0, oc0, h0, b, tid); CP_COMMIT();
    load_chunk2(sb0 + ST2_BYTES, 1, oc0, h0, b, tid); CP_COMMIT();

    for (int it = 0; it < 36; it++) {
        uint32_t sb = sb0 + (uint32_t)(it & 1) * ST2_BYTES;
        CP_WAIT1();
        __syncthreads();
        uint32_t sW = sb, sX = sb + W_BYTES;

#pragma unroll
        for (int wt = 0; wt < 3; wt++) {
            uint32_t xrow = (uint32_t)(hsub * 130 + wbase + wt);
#pragma unroll
            for (int kb = 0; kb < 64; kb += 32) {
                uint32_t bhi[8][2], af[4][4], t4[4];
#pragma unroll
                for (int u = 0; u < 4; u++) {
                    ldsm4(t4, sX + (xrow + u * 16 + bN) * 80 + kb + bK);
                    bhi[2 * u][0] = t4[0]; bhi[2 * u][1] = t4[1];
                    bhi[2 * u + 1][0] = t4[2]; bhi[2 * u + 1][1] = t4[3];
                }
                // pass1: Whi * Xhi
#pragma unroll
                for (int mi = 0; mi < 4; mi++)
                    ldsm4(af[mi], sW + ((wt * 2 + 0) * 128 + mw + mi * 16 + aRow) * 80
                                     + kb + aK);
#pragma unroll
                for (int mi = 0; mi < 4; mi++)
#pragma unroll
                    for (int ni = 0; ni < 8; ni++) mma16816(acc[mi][ni], af[mi], bhi[ni]);
                // pass2: Wlo * Xhi
#pragma unroll
                for (int mi = 0; mi < 4; mi++)
                    ldsm4(af[mi], sW + ((wt * 2 + 1) * 128 + mw + mi * 16 + aRow) * 80
                                     + kb + aK);
#pragma unroll
                for (int mi = 0; mi < 4; mi++)
#pragma unroll
                    for (int ni = 0; ni < 8; ni++) mma16816(acc[mi][ni], af[mi], bhi[ni]);
            }
        }
        __syncthreads();
        if (it + 2 < 36) load_chunk2(sb, it + 2, oc0, h0, b, tid);
        CP_COMMIT();   // empty group at tail keeps wait_group accounting valid
    }

    // epilogue: acc -> g_y2 (+bias)
    int g = lane >> 2, tg = lane & 3;
#pragma unroll
    for (int mi = 0; mi < 4; mi++) {
        int m = oc0 + mw + mi * 16 + g;
        float bs0 = bias[m], bs1 = bias[m + 8];
#pragma unroll
        for (int ni = 0; ni < 8; ni++) {
            int n = nw + ni * 8 + tg * 2;
            int h = h0 + (n >> 7), w = n & 127;
            float* p = g_y2 + ((size_t)b * 384 + m) * SPX + h * 128 + w;
            p[0] = acc[mi][ni][0] + bs0;
            p[1] = acc[mi][ni][1] + bs0;
            float* p2 = p + 8 * SPX;
            p2[0] = acc[mi][ni][2] + bs1;
            p2[1] = acc[mi][ni][3] + bs1;
        }
    }
}

// ------------------- inverse L2 norms for q,k -------------------------------
__global__ void norms_kernel()
{
    int bi_ = blockIdx.x;
    int ch = bi_ & 127, qk = (bi_ >> 7) & 1, b = bi_ >> 8;
    const float4* p = (const float4*)(g_y2 + b * 384 * SPX + (qk * 128 + ch) * SPX);
    float ss = 0.f;
    for (int i = threadIdx.x; i < 4096; i += 256) {
        float4 v = p[i];
        ss += v.x * v.x + v.y * v.y + v.z * v.z + v.w * v.w;
    }
    __shared__ float red[256];
    red[threadIdx.x] = ss;
    __syncthreads();
    for (int o = 128; o > 0; o >>= 1) {
        if (threadIdx.x < o) red[threadIdx.x] += red[threadIdx.x + o];
        __syncthreads();
    }
    if (threadIdx.x == 0) g_scale[bi_] = 1.f / fmaxf(sqrtf(red[0]), 1e-12f);
}

// ------------------- raw gram q k^T (s-split + atomics) ----------------------
__global__ void gram_kernel()
{
    __shared__ float Qs[32 * 129];
    __shared__ float Ks[32 * 129];
    int bi_ = blockIdx.x;
    int split = bi_ & 127;
    int h = (bi_ >> 7) & 3;
    int b = bi_ >> 9;
    int s0 = split * 128;
    const float* gQ = g_y2 + b * 384 * SPX + (h * 32) * SPX + s0;
    const float* gK = gQ + 128 * SPX;
    int tid = threadIdx.x;
    for (int idx = tid; idx < 4096; idx += 256) {
        int row = idx >> 7, col = idx & 127;
        Qs[row * 129 + col] = gQ[row * SPX + col];
        Ks[row * 129 + col] = gK[row * SPX + col];
    }
    __syncthreads();
    int c = tid >> 3, d0 = (tid & 7) * 4;
    float a0 = 0.f, a1 = 0.f, a2 = 0.f, a3 = 0.f;
    const float* qrow = &Qs[c * 129];
#pragma unroll 4
    for (int s = 0; s < 128; s++) {
        float qv = qrow[s];
        a0 += qv * Ks[(d0 + 0) * 129 + s];
        a1 += qv * Ks[(d0 + 1) * 129 + s];
        a2 += qv * Ks[(d0 + 2) * 129 + s];
        a3 += qv * Ks[(d0 + 3) * 129 + s];
    }
    float* Gp = &g_G[(b * 4 + h) * 1024 + c * 32 + d0];
    atomicAdd(Gp + 0, a0); atomicAdd(Gp + 1, a1);
    atomicAdd(Gp + 2, a2); atomicAdd(Gp + 3, a3);
}

// ------------------- scale + softmax over d ---------------------------------
__global__ void softmax_kernel(const float* __restrict__ temp)
{
    int bi_ = blockIdx.x;
    int c = bi_ & 31;
    int bh = bi_ >> 5;
    int h = bh & 3, b = bh >> 2;
    int d = threadIdx.x;
    float g = g_G[bh * 1024 + c * 32 + d]
            * g_scale[b * 256 + h * 32 + c]
            * g_scale[b * 256 + 128 + h * 32 + d]
            * temp[h];
    float mx = g;
    for (int o = 16; o > 0; o >>= 1) mx = fmaxf(mx, __shfl_xor_sync(0xffffffffu, mx, o));
    float e = expf(g - mx);
    float sm = e;
    for (int o = 16; o > 0; o >>= 1) sm += __shfl_xor_sync(0xffffffffu, sm, o);
    g_A[bh * 1024 + c * 32 + d] = e / sm;
}

// ------------------- fold attention into output conv: M = Wpo @ A ------------
// 128 blocks x 256 thr: t -> (b, oc, h*32+d); 32 MACs each
__global__ void fold_po()
{
    int t = blockIdx.x * 256 + threadIdx.x;
    int b  = t >> 14;
    int oc = (t >> 7) & 127;
    int hd = t & 127;
    int h = hd >> 5, d = hd & 31;
    const float* wrow = g_Wpo + oc * 128 + h * 32;
    const float* arow = g_A + ((b * 4 + h) << 10) + d;   // A[c][d], stride 32 over c
    float s = 0.f;
#pragma unroll
    for (int c = 0; c < 32; c++) s += wrow[c] * arow[c * 32];
    g_M[t] = s;
}

// ---------------------------------------------------------------------------
extern "C" void kernel_launch(void* const* d_in, const int* in_sizes, int n_in,
                              void* d_out, int out_size)
{
    const float* x     = (const float*)d_in[0];
    const float* qkv_r = (const float*)d_in[1];
    const float* qkv_i = (const float*)d_in[2];
    const float* qkv_j = (const float*)d_in[3];
    const float* qkv_k = (const float*)d_in[4];
    const float* qkv_b = (const float*)d_in[5];
    const float* dw_r  = (const float*)d_in[6];
    const float* dw_i  = (const float*)d_in[7];
    const float* dw_j  = (const float*)d_in[8];
    const float* dw_k  = (const float*)d_in[9];
    const float* dw_b  = (const float*)d_in[10];
    const float* po_r  = (const float*)d_in[11];
    const float* po_i  = (const float*)d_in[12];
    const float* po_j  = (const float*)d_in[13];
    const float* po_k  = (const float*)d_in[14];
    const float* po_b  = (const float*)d_in[15];
    const float* temp  = (const float*)d_in[16];
    float* out = (float*)d_out;

    cudaFuncSetAttribute(conv3x3_hmma, cudaFuncAttributeMaxDynamicSharedMemorySize,
                         CONV_SMEM);

    expand_small<<<288, 256>>>(qkv_r, qkv_i, qkv_j, qkv_k, po_r, po_i, po_j, po_k);
    expand_dw<<<5184, 256>>>(dw_r, dw_i, dw_j, dw_k);
    zero_pad<<<1032, 96>>>();

    gemm1x1<<<dim3(6, 256, 2), 256>>>(0, x, nullptr, qkv_b);        // 1x1 qkv conv
    conv3x3_hmma<<<dim3(3, 64, 2), 256, CONV_SMEM>>>(dw_b);         // 3x3 conv (HMMA)
    norms_kernel<<<512, 256>>>();
    gram_kernel<<<1024, 256>>>();
    softmax_kernel<<<256, 32>>>(temp);
    fold_po<<<128, 256>>>();
    gemm1x1<<<dim3(2, 256, 2), 256>>>(1, nullptr, out, po_b);       // out = M @ v
}

// round 15
// speedup vs baseline: 4.3034x; 1.1082x over previous
#include <cuda_runtime.h>
#include <cuda_fp16.h>
#include <cuda_bf16.h>
#include <cstdint>

// ---------------------------------------------------------------------------
// QAttention — round 15:
//  * qkv 1x1 conv on HMMA (exact 3-term fp16 split of W and x)
//  * conv3x3 HMMA 2-term split (unchanged from r12)
//  * norms fused into gram (sum-of-squares from smem tiles)
//  * attention folded into output conv (M = Wpo @ A), out = M @ v (FFMA2)
// ---------------------------------------------------------------------------

#define SPX 16384           // H*W
#define NB  2               // batch

// ------------------- device scratch (no allocations allowed) ----------------
__device__ __half g_Wqh[384 * 128];       // qkv weights hi
__device__ __half g_Wql[384 * 128];       // qkv weights lo
__device__ __half g_Wh[9 * 384 * 384];    // [tap][oc][ic] fp16 hi
__device__ __half g_Wl[9 * 384 * 384];    // [tap][oc][ic] fp16 lo
__device__ float  g_Wpo [128 * 128];
__device__ float  g_M   [NB * 128 * 128]; // folded Wpo @ attn
__device__ __half g_x16h[NB * SPX * 128]; // x transposed [b][px][ic] hi
__device__ __half g_x16l[NB * SPX * 128]; // x transposed [b][px][ic] lo
__device__ __half g_xh[NB * 130 * 130 * 384];  // padded channel-last act hi
__device__ float  g_y2  [NB * 384 * SPX];
__device__ float  g_ssq [NB * 256];       // sum-of-squares for q,k rows
__device__ float  g_G   [NB * 4 * 1024];
__device__ float  g_A   [NB * 4 * 1024];

// Hamilton block table
__device__ __forceinline__ void ham(int bo, int bi, int& src, float& sgn) {
    const int   SRC[4][4] = {{0,1,2,3},{1,0,3,2},{2,3,0,1},{3,2,1,0}};
    const float SGN[4][4] = {{1.f,-1.f,-1.f,-1.f},
                             {1.f, 1.f,-1.f, 1.f},
                             {1.f, 1.f, 1.f,-1.f},
                             {1.f,-1.f, 1.f, 1.f}};
    src = SRC[bo][bi];
    sgn = SGN[bo][bi];
}

// ------------------- PTX helpers --------------------------------------------
__device__ __forceinline__ uint32_t smem_u32(const void* p) {
    uint32_t a;
    asm("{ .reg .u64 t; cvta.to.shared.u64 t, %1; cvt.u32.u64 %0, t; }"
        : "=r"(a) : "l"(p));
    return a;
}
__device__ __forceinline__ void cpa16(uint32_t dst, const void* src) {
    asm volatile("cp.async.cg.shared.global [%0], [%1], 16;" :: "r"(dst), "l"(src));
}
#define CP_COMMIT() asm volatile("cp.async.commit_group;" ::: "memory")
#define CP_WAIT1()  asm volatile("cp.async.wait_group 1;"  ::: "memory")

__device__ __forceinline__ void ldsm4(uint32_t a[4], uint32_t addr) {
    asm volatile("ldmatrix.sync.aligned.m8n8.x4.shared.b16 {%0,%1,%2,%3}, [%4];"
                 : "=r"(a[0]), "=r"(a[1]), "=r"(a[2]), "=r"(a[3]) : "r"(addr));
}
__device__ __forceinline__ void mma16816(float d[4], const uint32_t a[4],
                                         const uint32_t b[2]) {
    asm volatile(
        "mma.sync.aligned.m16n8k16.row.col.f32.f16.f16.f32 "
        "{%0,%1,%2,%3},{%4,%5,%6,%7},{%8,%9},{%0,%1,%2,%3};"
        : "+f"(d[0]), "+f"(d[1]), "+f"(d[2]), "+f"(d[3])
        : "r"(a[0]), "r"(a[1]), "r"(a[2]), "r"(a[3]), "r"(b[0]), "r"(b[1]));
}
// packed f32x2
__device__ __forceinline__ void fma2(unsigned long long& d,
                                     unsigned long long a, unsigned long long b) {
    asm("fma.rn.f32x2 %0, %1, %2, %0;" : "+l"(d) : "l"(a), "l"(b));
}
__device__ __forceinline__ float2 unpk(unsigned long long v) {
    float2 r; asm("mov.b64 {%0,%1}, %2;" : "=f"(r.x), "=f"(r.y) : "l"(v)); return r;
}

// ------------------- weight expansion + zero --------------------------------
// 290 blocks x 256 = 74240 = 49152 Wqkv + 16384 Wpo + 8192 Gzero + 512 ssq
__global__ void expand_small(const float* __restrict__ qr, const float* __restrict__ qi,
                             const float* __restrict__ qj, const float* __restrict__ qk,
                             const float* __restrict__ pr, const float* __restrict__ pi,
                             const float* __restrict__ pj, const float* __restrict__ pk)
{
    int t = blockIdx.x * 256 + threadIdx.x;
    if (t < 49152) {
        int oc = t >> 7, ic = t & 127;
        int bo = oc / 96, oo = oc - bo * 96;
        int bi = ic >> 5, ii = ic & 31;
        const float* srcs[4] = {qr, qi, qj, qk};
        int s; float sg; ham(bo, bi, s, sg);
        float w = sg * srcs[s][oo * 32 + ii];
        __half hi = __float2half(w);
        g_Wqh[t] = hi;
        g_Wql[t] = __float2half(w - __half2float(hi));
    } else if (t < 65536) {
        int e = t - 49152;
        int oc = e >> 7, ic = e & 127;
        int bo = oc >> 5, oo = oc & 31;
        int bi = ic >> 5, ii = ic & 31;
        const float* srcs[4] = {pr, pi, pj, pk};
        int s; float sg; ham(bo, bi, s, sg);
        g_Wpo[e] = sg * srcs[s][oo * 32 + ii];
    } else if (t < 73728) {
        g_G[t - 65536] = 0.f;
    } else if (t < 74240) {
        g_ssq[t - 73728] = 0.f;
    }
}

// [tap][oc][ic] hi/lo fp16: 5184 blocks x 256 thr
__global__ void expand_dw(const float* __restrict__ dr, const float* __restrict__ di,
                          const float* __restrict__ dj, const float* __restrict__ dk)
{
    int t = blockIdx.x * 256 + threadIdx.x;
    int oc  = t / 3456;
    int rem = t - oc * 3456;
    int ic  = rem / 9;
    int tap = rem - ic * 9;
    int bo = oc / 96, oo = oc - bo * 96;
    int bi = ic / 96, ii = ic - bi * 96;
    const float* srcs[4] = {dr, di, dj, dk};
    int s; float sg; ham(bo, bi, s, sg);
    float w = sg * srcs[s][(oo * 96 + ii) * 9 + tap];
    __half hi = __float2half(w);
    __half lo = __float2half(w - __half2float(hi));
    int idx = tap * 147456 + oc * 384 + ic;
    g_Wh[idx] = hi;
    g_Wl[idx] = lo;
}

// ------------------- zero the pad border of g_xh ------------------------------
__global__ void zero_pad()
{
    int bp = blockIdx.x;
    int b = bp >= 516; int e = bp - b * 516;
    int row, col;
    if (e < 130)      { row = 0;   col = e; }
    else if (e < 260) { row = 129; col = e - 130; }
    else { int e2 = e - 260; row = 1 + (e2 >> 1); col = (e2 & 1) ? 129 : 0; }
    size_t base = ((size_t)(b * 130 + row) * 130 + col) * 384;
    *(float2*)((char*)g_xh + base * 2 + threadIdx.x * 8) = make_float2(0.f, 0.f);
}

// ------------------- x transpose + fp16 hi/lo split --------------------------
// x [b][ic][px] fp32 -> g_x16h/l [b][px][ic] fp16.  grid (4, 512, 2), 256 thr.
__global__ void xsplit(const float* __restrict__ x)
{
    __shared__ float t[32][33];
    int ic0 = blockIdx.x * 32, px0 = blockIdx.y * 32, b = blockIdx.z;
    int tid = threadIdx.x;
#pragma unroll
    for (int i = 0; i < 4; i++) {
        int idx = tid + i * 256;
        int icl = idx >> 5, pxl = idx & 31;
        t[icl][pxl] = x[((size_t)(b * 128) + ic0 + icl) * SPX + px0 + pxl];
    }
    __syncthreads();
#pragma unroll
    for (int i = 0; i < 4; i++) {
        int idx = tid + i * 256;
        int pxl = idx >> 5, icl = idx & 31;
        float v = t[icl][pxl];
        __half hi = __float2half(v);
        size_t o = ((size_t)b * SPX + px0 + pxl) * 128 + ic0 + icl;
        g_x16h[o] = hi;
        g_x16l[o] = __float2half(v - __half2float(hi));
    }
}

// ------------------- qkv 1x1 conv: HMMA, exact 3-term split ------------------
// CTA: 128 oc x 256 px, K=128 in 4 chunks of 32. 2-stage cp.async.
// stage: W hi/lo 2x128 rows + X hi/lo 2x256 rows, 80B pitch.
#define QW_BYTES 20480               // 2*128*80
#define QX_BYTES 40960               // 2*256*80
#define QST      (QW_BYTES + QX_BYTES)   // 61440
#define QSMEM    (2 * QST)               // 122880  (>= 256*272 staging)

__device__ __forceinline__ void load_qchunk(uint32_t sb, int chunk, int oc0,
                                            int px0, int b, int tid)
{
    int k0 = chunk * 32;
#pragma unroll
    for (int i = 0; i < 4; i++) {            // W: 1024 16B ops
        int gid  = tid + i * 256;
        int comb = gid >> 9;                 // 0=hi,1=lo
        int row  = (gid >> 2) & 127;
        int q    = gid & 3;
        const __half* src = (comb ? g_Wql : g_Wqh)
            + (size_t)(oc0 + row) * 128 + k0 + q * 8;
        cpa16(sb + (uint32_t)(comb * 128 + row) * 80 + q * 16, src);
    }
#pragma unroll
    for (int i = 0; i < 8; i++) {            // X: 2048 16B ops
        int gid  = tid + i * 256;
        int comb = gid >> 10;
        int row  = (gid >> 2) & 255;
        int q    = gid & 3;
        const __half* src = (comb ? g_x16l : g_x16h)
            + ((size_t)b * SPX + px0 + row) * 128 + k0 + q * 8;
        cpa16(sb + QW_BYTES + (uint32_t)(comb * 256 + row) * 80 + q * 16, src);
    }
}

__global__ __launch_bounds__(256, 1) void qkv_hmma(const float* __restrict__ bias)
{
    extern __shared__ char smem[];
    uint32_t sb0 = smem_u32(smem);
    int tid  = threadIdx.x;
    int lane = tid & 31, wid = tid >> 5;
    int oc0 = blockIdx.x * 128;
    int px0 = blockIdx.y * 256;
    int b   = blockIdx.z;

    int mw = (wid & 1) * 64;
    int nw = (wid >> 1) * 64;
    int r = lane & 7, j = lane >> 3;
    uint32_t aRow = (uint32_t)((j & 1) * 8 + r);
    uint32_t aK   = (uint32_t)((j >> 1) * 16);
    uint32_t bN   = (uint32_t)((j >> 1) * 8 + r);
    uint32_t bK   = (uint32_t)((j & 1) * 16);

    float acc[4][8][4];
#pragma unroll
    for (int mi = 0; mi < 4; mi++)
#pragma unroll
        for (int ni = 0; ni < 8; ni++)
#pragma unroll
            for (int e = 0; e < 4; e++) acc[mi][ni][e] = 0.f;

    load_qchunk(sb0,       0, oc0, px0, b, tid); CP_COMMIT();
    load_qchunk(sb0 + QST, 1, oc0, px0, b, tid); CP_COMMIT();

    for (int it = 0; it < 4; it++) {
        uint32_t sb = sb0 + (uint32_t)(it & 1) * QST;
        CP_WAIT1();
        __syncthreads();
        uint32_t sXh = sb + QW_BYTES, sXl = sXh + 256 * 80;

#pragma unroll
        for (int kb = 0; kb < 64; kb += 32) {
            uint32_t bhi[8][2], blo[8][2], ah[4][4], al[4][4], t4[4];
#pragma unroll
            for (int u = 0; u < 4; u++) {
                ldsm4(t4, sXh + (nw + u * 16 + bN) * 80 + kb + bK);
                bhi[2 * u][0] = t4[0]; bhi[2 * u][1] = t4[1];
                bhi[2 * u + 1][0] = t4[2]; bhi[2 * u + 1][1] = t4[3];
            }
#pragma unroll
            for (int u = 0; u < 4; u++) {
                ldsm4(t4, sXl + (nw + u * 16 + bN) * 80 + kb + bK);
                blo[2 * u][0] = t4[0]; blo[2 * u][1] = t4[1];
                blo[2 * u + 1][0] = t4[2]; blo[2 * u + 1][1] = t4[3];
            }
#pragma unroll
            for (int mi = 0; mi < 4; mi++)
                ldsm4(ah[mi], sb + (mw + mi * 16 + aRow) * 80 + kb + aK);
#pragma unroll
            for (int mi = 0; mi < 4; mi++)
                ldsm4(al[mi], sb + (128 + mw + mi * 16 + aRow) * 80 + kb + aK);
            // Whi*Xhi + Wlo*Xhi + Whi*Xlo
#pragma unroll
            for (int mi = 0; mi < 4; mi++)
#pragma unroll
                for (int ni = 0; ni < 8; ni++) mma16816(acc[mi][ni], ah[mi], bhi[ni]);
#pragma unroll
            for (int mi = 0; mi < 4; mi++)
#pragma unroll
                for (int ni = 0; ni < 8; ni++) mma16816(acc[mi][ni], al[mi], bhi[ni]);
#pragma unroll
            for (int mi = 0; mi < 4; mi++)
#pragma unroll
                for (int ni = 0; ni < 8; ni++) mma16816(acc[mi][ni], ah[mi], blo[ni]);
        }
        __syncthreads();
        if (it + 2 < 4) load_qchunk(sb, it + 2, oc0, px0, b, tid);
        CP_COMMIT();
    }

    // stage output tile [n px][m oc] fp16 in smem (pitch 272), then coalesced STG
    int g = lane >> 2, tg = lane & 3;
#pragma unroll
    for (int mi = 0; mi < 4; mi++) {
        int ml = mw + mi * 16 + g;
        float bs0 = bias[oc0 + ml], bs1 = bias[oc0 + ml + 8];
#pragma unroll
        for (int ni = 0; ni < 8; ni++) {
            int n = nw + ni * 8 + tg * 2;
            *(__half*)(smem + n * 272 + ml * 2)
                = __float2half(acc[mi][ni][0] + bs0);
            *(__half*)(smem + (n + 1) * 272 + ml * 2)
                = __float2half(acc[mi][ni][1] + bs0);
            *(__half*)(smem + n * 272 + (ml + 8) * 2)
                = __float2half(acc[mi][ni][2] + bs1);
            *(__half*)(smem + (n + 1) * 272 + (ml + 8) * 2)
                = __float2half(acc[mi][ni][3] + bs1);
        }
    }
    __syncthreads();
    {
        int n = tid;
        int px = px0 + n, h = px >> 7, w = px & 127;
        const uint4* srow = (const uint4*)(smem + n * 272);
        uint4* drow = (uint4*)(g_xh + ((size_t)(b * 130 + h + 1) * 130 + w + 1) * 384
                               + oc0);
#pragma unroll
        for (int i = 0; i < 16; i++) drow[i] = srow[i];
    }
}

// ------------------- 3x3 conv: HMMA implicit GEMM, 2-term split --------------
#define W_BYTES   61440              // 6*128*80
#define X_BYTES   20800              // 260*80
#define ST2_BYTES (W_BYTES + X_BYTES)   // 82240
#define CONV_SMEM (2 * ST2_BYTES)       // 164480

__device__ __forceinline__ void load_chunk2(uint32_t sb, int chunk, int oc0,
                                            int h0, int b, int tid)
{
    int dh = chunk / 12;
    int k0 = (chunk - dh * 12) * 32;
#pragma unroll
    for (int i = 0; i < 12; i++) {
        int gid  = tid + i * 256;
        int comb = gid >> 9;              // 0..5 = wt*2+hl
        int wt   = comb >> 1, hl = comb & 1;
        int row  = (gid >> 2) & 127;
        int q    = gid & 3;
        const __half* src = (hl ? g_Wl : g_Wh)
            + (size_t)((dh * 3 + wt) * 384 + oc0 + row) * 384 + k0 + q * 8;
        cpa16(sb + (uint32_t)(comb * 128 + row) * 80 + q * 16, src);
    }
#pragma unroll
    for (int i = 0; i < 5; i++) {
        int gid = tid + i * 256;
        if (gid < 1040) {
            int row = gid >> 2, q = gid & 3;
            int hsub = row >= 130;
            int px = row - hsub * 130;
            const __half* src = g_xh
                + ((size_t)(b * 130 + h0 + hsub + dh) * 130 + px) * 384 + k0 + q * 8;
            cpa16(sb + W_BYTES + (uint32_t)row * 80 + q * 16, src);
        }
    }
}

__global__ __launch_bounds__(256, 1) void conv3x3_hmma(const float* __restrict__ bias)
{
    extern __shared__ char smem[];
    uint32_t sb0 = smem_u32(smem);
    int tid  = threadIdx.x;
    int lane = tid & 31, wid = tid >> 5;
    int oc0 = blockIdx.x * 128;
    int h0  = blockIdx.y * 2;
    int b   = blockIdx.z;

    int mw = (wid & 1) * 64;
    int nw = (wid >> 1) * 64;
    int r = lane & 7, j = lane >> 3;
    uint32_t aRow = (uint32_t)((j & 1) * 8 + r);
    uint32_t aK   = (uint32_t)((j >> 1) * 16);
    uint32_t bN   = (uint32_t)((j >> 1) * 8 + r);
    uint32_t bK   = (uint32_t)((j & 1) * 16);
    int hsub  = nw >> 7;
    int wbase = nw & 127;

    float acc[4][8][4];
#pragma unroll
    for (int mi = 0; mi < 4; mi++)
#pragma unroll
        for (int ni = 0; ni < 8; ni++)
#pragma unroll
            for (int e = 0; e < 4; e++) acc[mi][ni][e] = 0.f;

    load_chunk2(sb0,             0, oc0, h0, b, tid); CP_COMMIT();
    load_chunk2(sb0 + ST2_BYTES, 1, oc0, h0, b, tid); CP_COMMIT();

    for (int it = 0; it < 36; it++) {
        uint32_t sb = sb0 + (uint32_t)(it & 1) * ST2_BYTES;
        CP_WAIT1();
        __syncthreads();
        uint32_t sW = sb, sX = sb + W_BYTES;

#pragma unroll
        for (int wt = 0; wt < 3; wt++) {
            uint32_t xrow = (uint32_t)(hsub * 130 + wbase + wt);
#pragma unroll
            for (int kb = 0; kb < 64; kb += 32) {
                uint32_t bhi[8][2], af[4][4], t4[4];
#pragma unroll
                for (int u = 0; u < 4; u++) {
                    ldsm4(t4, sX + (xrow + u * 16 + bN) * 80 + kb + bK);
                    bhi[2 * u][0] = t4[0]; bhi[2 * u][1] = t4[1];
                    bhi[2 * u + 1][0] = t4[2]; bhi[2 * u + 1][1] = t4[3];
                }
#pragma unroll
                for (int mi = 0; mi < 4; mi++)
                    ldsm4(af[mi], sW + ((wt * 2 + 0) * 128 + mw + mi * 16 + aRow) * 80
                                     + kb + aK);
#pragma unroll
                for (int mi = 0; mi < 4; mi++)
#pragma unroll
                    for (int ni = 0; ni < 8; ni++) mma16816(acc[mi][ni], af[mi], bhi[ni]);
#pragma unroll
                for (int mi = 0; mi < 4; mi++)
                    ldsm4(af[mi], sW + ((wt * 2 + 1) * 128 + mw + mi * 16 + aRow) * 80
                                     + kb + aK);
#pragma unroll
                for (int mi = 0; mi < 4; mi++)
#pragma unroll
                    for (int ni = 0; ni < 8; ni++) mma16816(acc[mi][ni], af[mi], bhi[ni]);
            }
        }
        __syncthreads();
        if (it + 2 < 36) load_chunk2(sb, it + 2, oc0, h0, b, tid);
        CP_COMMIT();
    }

    int g = lane >> 2, tg = lane & 3;
#pragma unroll
    for (int mi = 0; mi < 4; mi++) {
        int m = oc0 + mw + mi * 16 + g;
        float bs0 = bias[m], bs1 = bias[m + 8];
#pragma unroll
        for (int ni = 0; ni < 8; ni++) {
            int n = nw + ni * 8 + tg * 2;
            int h = h0 + (n >> 7), w = n & 127;
            float* p = g_y2 + ((size_t)b * 384 + m) * SPX + h * 128 + w;
            p[0] = acc[mi][ni][0] + bs0;
            p[1] = acc[mi][ni][1] + bs0;
            float* p2 = p + 8 * SPX;
            p2[0] = acc[mi][ni][2] + bs1;
            p2[1] = acc[mi][ni][3] + bs1;
        }
    }
}

// ------------------- gram q k^T + fused sum-of-squares -----------------------
__global__ void gram_kernel()
{
    __shared__ float Qs[32 * 129];
    __shared__ float Ks[32 * 129];
    int bi_ = blockIdx.x;
    int split = bi_ & 127;
    int h = (bi_ >> 7) & 3;
    int b = bi_ >> 9;
    int s0 = split * 128;
    const float* gQ = g_y2 + b * 384 * SPX + (h * 32) * SPX + s0;
    const float* gK = gQ + 128 * SPX;
    int tid = threadIdx.x;
    for (int idx = tid; idx < 4096; idx += 256) {
        int row = idx >> 7, col = idx & 127;
        Qs[row * 129 + col] = gQ[row * SPX + col];
        Ks[row * 129 + col] = gK[row * SPX + col];
    }
    __syncthreads();
    int c = tid >> 3, d0 = (tid & 7) * 4;
    float a0 = 0.f, a1 = 0.f, a2 = 0.f, a3 = 0.f;
    const float* qrow = &Qs[c * 129];
#pragma unroll 4
    for (int s = 0; s < 128; s++) {
        float qv = qrow[s];
        a0 += qv * Ks[(d0 + 0) * 129 + s];
        a1 += qv * Ks[(d0 + 1) * 129 + s];
        a2 += qv * Ks[(d0 + 2) * 129 + s];
        a3 += qv * Ks[(d0 + 3) * 129 + s];
    }
    float* Gp = &g_G[(b * 4 + h) * 1024 + c * 32 + d0];
    atomicAdd(Gp + 0, a0); atomicAdd(Gp + 1, a1);
    atomicAdd(Gp + 2, a2); atomicAdd(Gp + 3, a3);

    // fused sum-of-squares for q,k row norms (c = row, 8 threads per row)
    {
        int gg = tid & 7;
        float sq = 0.f, sk = 0.f;
        const float* kr = &Ks[c * 129];
#pragma unroll
        for (int s2 = 0; s2 < 16; s2++) {
            float v = qrow[gg * 16 + s2]; sq += v * v;
            float u = kr[gg * 16 + s2];   sk += u * u;
        }
#pragma unroll
        for (int o = 4; o > 0; o >>= 1) {
            sq += __shfl_xor_sync(0xffffffffu, sq, o);
            sk += __shfl_xor_sync(0xffffffffu, sk, o);
        }
        if (gg == 0) {
            atomicAdd(&g_ssq[b * 256 + h * 32 + c], sq);
            atomicAdd(&g_ssq[b * 256 + 128 + h * 32 + c], sk);
        }
    }
}

// ------------------- scale + softmax over d ---------------------------------
__global__ void softmax_kernel(const float* __restrict__ temp)
{
    int bi_ = blockIdx.x;
    int c = bi_ & 31;
    int bh = bi_ >> 5;
    int h = bh & 3, b = bh >> 2;
    int d = threadIdx.x;
    float qsc = 1.f / fmaxf(sqrtf(g_ssq[b * 256 + h * 32 + c]), 1e-12f);
    float ksc = 1.f / fmaxf(sqrtf(g_ssq[b * 256 + 128 + h * 32 + d]), 1e-12f);
    float g = g_G[bh * 1024 + c * 32 + d] * qsc * ksc * temp[h];
    float mx = g;
    for (int o = 16; o > 0; o >>= 1) mx = fmaxf(mx, __shfl_xor_sync(0xffffffffu, mx, o));
    float e = expf(g - mx);
    float sm = e;
    for (int o = 16; o > 0; o >>= 1) sm += __shfl_xor_sync(0xffffffffu, sm, o);
    g_A[bh * 1024 + c * 32 + d] = e / sm;
}

// ------------------- fold attention into output conv: M = Wpo @ A ------------
__global__ void fold_po()
{
    int t = blockIdx.x * 256 + threadIdx.x;
    int b  = t >> 14;
    int oc = (t >> 7) & 127;
    int hd = t & 127;
    int h = hd >> 5, d = hd & 31;
    const float* wrow = g_Wpo + oc * 128 + h * 32;
    const float* arow = g_A + ((b * 4 + h) << 10) + d;
    float s = 0.f;
#pragma unroll
    for (int c = 0; c < 32; c++) s += wrow[c] * arow[c * 32];
    g_M[t] = s;
}

// ------------------- out = M @ v  (FFMA2 GEMM, K=128) ------------------------
__global__ void gemm_out(float* __restrict__ Oout, const float* __restrict__ bias)
{
    __shared__ __align__(16) float2 As2[16][66];
    __shared__ __align__(16) float  Bs[16][64];
    int b  = blockIdx.z;
    const float* W  = g_M + b * 16384;
    const float* Bb = g_y2 + (size_t)b * 384 * SPX + 256 * SPX;

    int m0 = blockIdx.x * 64, n0 = blockIdx.y * 64;
    int tid = threadIdx.x;
    int tx4 = (tid & 15) * 4, ty4 = (tid >> 4) * 4;
    int lm  = tid >> 2,  lk4 = (tid & 3) * 4;
    int lk  = tid >> 4,  ln4 = (tid & 15) * 4;

    unsigned long long acc2[4][2];
#pragma unroll
    for (int i = 0; i < 4; i++) { acc2[i][0] = 0ull; acc2[i][1] = 0ull; }

    for (int k0 = 0; k0 < 128; k0 += 16) {
        float4 a4 = *(const float4*)&W[(m0 + lm) * 128 + k0 + lk4];
        As2[lk4 + 0][lm] = make_float2(a4.x, a4.x);
        As2[lk4 + 1][lm] = make_float2(a4.y, a4.y);
        As2[lk4 + 2][lm] = make_float2(a4.z, a4.z);
        As2[lk4 + 3][lm] = make_float2(a4.w, a4.w);
        *(float4*)&Bs[lk][ln4] = *(const float4*)&Bb[(size_t)(k0 + lk) * SPX + n0 + ln4];
        __syncthreads();
#pragma unroll
        for (int kk = 0; kk < 16; kk++) {
            ulonglong2 bp  = *(const ulonglong2*)&Bs[kk][tx4];
            ulonglong2 a01 = *(const ulonglong2*)&As2[kk][ty4];
            ulonglong2 a23 = *(const ulonglong2*)&As2[kk][ty4 + 2];
            fma2(acc2[0][0], a01.x, bp.x); fma2(acc2[0][1], a01.x, bp.y);
            fma2(acc2[1][0], a01.y, bp.x); fma2(acc2[1][1], a01.y, bp.y);
            fma2(acc2[2][0], a23.x, bp.x); fma2(acc2[2][1], a23.x, bp.y);
            fma2(acc2[3][0], a23.y, bp.x); fma2(acc2[3][1], a23.y, bp.y);
        }
        __syncthreads();
    }

    float* Cb = Oout + (size_t)b * 128 * SPX;
#pragma unroll
    for (int i = 0; i < 4; i++) {
        float bs = bias[m0 + ty4 + i];
        float2 r0 = unpk(acc2[i][0]), r1 = unpk(acc2[i][1]);
        float4 v = make_float4(r0.x + bs, r0.y + bs, r1.x + bs, r1.y + bs);
        *(float4*)&Cb[(size_t)(m0 + ty4 + i) * SPX + n0 + tx4] = v;
    }
}

// ---------------------------------------------------------------------------
extern "C" void kernel_launch(void* const* d_in, const int* in_sizes, int n_in,
                              void* d_out, int out_size)
{
    const float* x     = (const float*)d_in[0];
    const float* qkv_r = (const float*)d_in[1];
    const float* qkv_i = (const float*)d_in[2];
    const float* qkv_j = (const float*)d_in[3];
    const float* qkv_k = (const float*)d_in[4];
    const float* qkv_b = (const float*)d_in[5];
    const float* dw_r  = (const float*)d_in[6];
    const float* dw_i  = (const float*)d_in[7];
    const float* dw_j  = (const float*)d_in[8];
    const float* dw_k  = (const float*)d_in[9];
    const float* dw_b  = (const float*)d_in[10];
    const float* po_r  = (const float*)d_in[11];
    const float* po_i  = (const float*)d_in[12];
    const float* po_j  = (const float*)d_in[13];
    const float* po_k  = (const float*)d_in[14];
    const float* po_b  = (const float*)d_in[15];
    const float* temp  = (const float*)d_in[16];
    float* out = (float*)d_out;

    cudaFuncSetAttribute(conv3x3_hmma, cudaFuncAttributeMaxDynamicSharedMemorySize,
                         CONV_SMEM);
    cudaFuncSetAttribute(qkv_hmma, cudaFuncAttributeMaxDynamicSharedMemorySize,
                         QSMEM);

    expand_small<<<290, 256>>>(qkv_r, qkv_i, qkv_j, qkv_k, po_r, po_i, po_j, po_k);
    expand_dw<<<5184, 256>>>(dw_r, dw_i, dw_j, dw_k);
    zero_pad<<<1032, 96>>>();
    xsplit<<<dim3(4, 512, 2), 256>>>(x);

    qkv_hmma<<<dim3(3, 64, 2), 256, QSMEM>>>(qkv_b);                // 1x1 qkv (HMMA)
    conv3x3_hmma<<<dim3(3, 64, 2), 256, CONV_SMEM>>>(dw_b);         // 3x3 conv (HMMA)
    gram_kernel<<<1024, 256>>>();                                   // gram + norms
    softmax_kernel<<<256, 32>>>(temp);
    fold_po<<<128, 256>>>();
    gemm_out<<<dim3(2, 256, 2), 256>>>(out, po_b);                  // out = M @ v
}